// round 9
// baseline (speedup 1.0000x reference)
#include <cuda_runtime.h>
#include <cuda_bf16.h>
#include <cuda_fp16.h>
#include <math.h>
#include <stdint.h>

// Problem constants
#define BS   128
#define NW   80
#define NP   128
#define NQ   36
#define DIM  768
#define TAU_INV 100.0f

#define PT   4            // patches per K2 block
#define NT   144          // PT*NQ columns per tile
#define FS   148          // F row stride in smem

// Scratch (device globals: no allocation allowed)
__device__ float g_pl [NP*NQ*DIM];    // 4608 x 768  : patch @ L^T
__device__ float g_wl [BS*NP*NQ];     // word_level [b][p][q]
__device__ float g_plv[BS*NW*NP];     // patch_level [b][w][p]
__device__ float g_sim[BS*NP];        // sim [b][p]

// ---------------------------------------------------------------------------
// split helpers
// ---------------------------------------------------------------------------
__device__ __forceinline__ uint32_t pack_f16(float lo_elem, float hi_elem) {
    uint32_t r;
    asm("cvt.rn.f16x2.f32 %0, %1, %2;" : "=r"(r) : "f"(hi_elem), "f"(lo_elem));
    return r;
}
__device__ __forceinline__ void split4_f16(float4 v, uint32_t* hp, uint32_t* lp) {
    float h0 = __half2float(__float2half_rn(v.x));
    float h1 = __half2float(__float2half_rn(v.y));
    float h2 = __half2float(__float2half_rn(v.z));
    float h3 = __half2float(__float2half_rn(v.w));
    hp[0] = pack_f16(h0, h1);
    hp[1] = pack_f16(h2, h3);
    lp[0] = pack_f16(v.x - h0, v.y - h1);
    lp[1] = pack_f16(v.z - h2, v.w - h3);
}
// scaled-residual variant for f16-accumulated cross products (scale = 2048)
__device__ __forceinline__ void split4_f16s(float4 v, uint32_t* hp, uint32_t* lp) {
    float h0 = __half2float(__float2half_rn(v.x));
    float h1 = __half2float(__float2half_rn(v.y));
    float h2 = __half2float(__float2half_rn(v.z));
    float h3 = __half2float(__float2half_rn(v.w));
    hp[0] = pack_f16(h0, h1);
    hp[1] = pack_f16(h2, h3);
    lp[0] = pack_f16((v.x - h0) * 2048.0f, (v.y - h1) * 2048.0f);
    lp[1] = pack_f16((v.z - h2) * 2048.0f, (v.w - h3) * 2048.0f);
}
__device__ __forceinline__ void mma_f16(float4& d,
    uint32_t a0, uint32_t a1, uint32_t a2, uint32_t a3,
    uint32_t b0, uint32_t b1) {
    asm volatile(
        "mma.sync.aligned.m16n8k16.row.col.f32.f16.f16.f32 "
        "{%0,%1,%2,%3}, {%4,%5,%6,%7}, {%8,%9}, {%0,%1,%2,%3};\n"
        : "+f"(d.x), "+f"(d.y), "+f"(d.z), "+f"(d.w)
        : "r"(a0), "r"(a1), "r"(a2), "r"(a3), "r"(b0), "r"(b1));
}
// f16-accumulator variant (the rate experiment)
__device__ __forceinline__ void mma_f16h(uint32_t& d0, uint32_t& d1,
    uint32_t a0, uint32_t a1, uint32_t a2, uint32_t a3,
    uint32_t b0, uint32_t b1) {
    asm volatile(
        "mma.sync.aligned.m16n8k16.row.col.f16.f16.f16.f16 "
        "{%0,%1}, {%2,%3,%4,%5}, {%6,%7}, {%0,%1};\n"
        : "+r"(d0), "+r"(d1)
        : "r"(a0), "r"(a1), "r"(a2), "r"(a3), "r"(b0), "r"(b1));
}

// ---------------------------------------------------------------------------
// K1 v2: pl = patch2d @ L^T via fp16 2-split mma (3 products, f32 acc).
// (unchanged from R8)
// ---------------------------------------------------------------------------
#define K1PRS 12
#define K1_STG 5376

__global__ void __launch_bounds__(256, 2) k1_plgemm(const float* __restrict__ patch,
                                                    const float* __restrict__ L) {
    extern __shared__ float smf[];
    uint32_t* smw = (uint32_t*)smf;
    const int tid = threadIdx.x;
    const int lane = tid & 31, wid = tid >> 5;
    const int g = lane >> 2, t4 = lane & 3;
    const int mw = wid >> 1, nw = wid & 1;
    const int m0 = blockIdx.y * 128;
    const int n0 = blockIdx.x * 96;
    const float* Ap = patch + (size_t)m0 * DIM;
    const float* Bp = L + (size_t)n0 * DIM;

    float4 pa[2], pb[2];
#pragma unroll
    for (int j = 0; j < 2; j++) {
        const int pos = tid + 256 * j;
        pa[j] = *(const float4*)&Ap[(pos >> 2) * DIM + 4 * (pos & 3)];
    }
#pragma unroll
    for (int j = 0; j < 2; j++) {
        const int pos = tid + 256 * j;
        if (pos < 384)
            pb[j] = *(const float4*)&Bp[(pos >> 2) * DIM + 4 * (pos & 3)];
    }

    float4 acc[2][6];
#pragma unroll
    for (int i = 0; i < 2; i++)
#pragma unroll
        for (int j = 0; j < 6; j++) acc[i][j] = make_float4(0.f, 0.f, 0.f, 0.f);

    for (int kc = 0; kc < 48; kc++) {
        __syncthreads();
        uint32_t* Ah = smw + (kc & 1) * K1_STG;
        uint32_t* Al = Ah + 1536;
        uint32_t* Bh = Ah + 3072;
        uint32_t* Bl = Ah + 4224;
#pragma unroll
        for (int j = 0; j < 2; j++) {
            const int pos = tid + 256 * j, r = pos >> 2, c4 = pos & 3;
            uint32_t hp[2], lp[2];
            split4_f16(pa[j], hp, lp);
            *(uint2*)&Ah[r * K1PRS + 2 * c4] = make_uint2(hp[0], hp[1]);
            *(uint2*)&Al[r * K1PRS + 2 * c4] = make_uint2(lp[0], lp[1]);
        }
#pragma unroll
        for (int j = 0; j < 2; j++) {
            const int pos = tid + 256 * j;
            if (pos < 384) {
                const int r = pos >> 2, c4 = pos & 3;
                uint32_t hp[2], lp[2];
                split4_f16(pb[j], hp, lp);
                *(uint2*)&Bh[r * K1PRS + 2 * c4] = make_uint2(hp[0], hp[1]);
                *(uint2*)&Bl[r * K1PRS + 2 * c4] = make_uint2(lp[0], lp[1]);
            }
        }
        __syncthreads();
        if (kc < 47) {
            const int kn = (kc + 1) * 16;
#pragma unroll
            for (int j = 0; j < 2; j++) {
                const int pos = tid + 256 * j;
                pa[j] = *(const float4*)&Ap[(pos >> 2) * DIM + kn + 4 * (pos & 3)];
            }
#pragma unroll
            for (int j = 0; j < 2; j++) {
                const int pos = tid + 256 * j;
                if (pos < 384)
                    pb[j] = *(const float4*)&Bp[(pos >> 2) * DIM + kn + 4 * (pos & 3)];
            }
        }
#pragma unroll
        for (int mt = 0; mt < 2; mt++) {
            const int arow = (mw * 32 + mt * 16 + g) * K1PRS + t4;
            const uint32_t ah0 = Ah[arow];
            const uint32_t ah1 = Ah[arow + 8 * K1PRS];
            const uint32_t ah2 = Ah[arow + 4];
            const uint32_t ah3 = Ah[arow + 8 * K1PRS + 4];
            const uint32_t al0 = Al[arow];
            const uint32_t al1 = Al[arow + 8 * K1PRS];
            const uint32_t al2 = Al[arow + 4];
            const uint32_t al3 = Al[arow + 8 * K1PRS + 4];
#pragma unroll
            for (int nt = 0; nt < 6; nt++) {
                const int brow = (nw * 48 + nt * 8 + g) * K1PRS + t4;
                const uint32_t bh0 = Bh[brow];
                const uint32_t bh1 = Bh[brow + 4];
                const uint32_t bl0 = Bl[brow];
                const uint32_t bl1 = Bl[brow + 4];
                mma_f16(acc[mt][nt], ah0, ah1, ah2, ah3, bh0, bh1);
                mma_f16(acc[mt][nt], ah0, ah1, ah2, ah3, bl0, bl1);
                mma_f16(acc[mt][nt], al0, al1, al2, al3, bh0, bh1);
            }
        }
    }

#pragma unroll
    for (int mt = 0; mt < 2; mt++) {
#pragma unroll
        for (int nt = 0; nt < 6; nt++) {
            const int row = m0 + mw * 32 + mt * 16 + g;
            const int col = n0 + nw * 48 + nt * 8 + 2 * t4;
            g_pl[(size_t)row * DIM + col]           = acc[mt][nt].x;
            g_pl[(size_t)row * DIM + col + 1]       = acc[mt][nt].y;
            g_pl[(size_t)(row + 8) * DIM + col]     = acc[mt][nt].z;
            g_pl[(size_t)(row + 8) * DIM + col + 1] = acc[mt][nt].w;
        }
    }
}

// ---------------------------------------------------------------------------
// K2 v6: fp16 split; hh -> f32-acc MMA, cross (hl+lh, residuals x2048) ->
// f16-acc MMAs. Register-G epilogue, 2 CTAs/SM.
// ---------------------------------------------------------------------------
#define SMW_BUF 8960
#define PRS 20          // pair-row stride in words

__global__ void __launch_bounds__(320, 2) k2_fine(const float* __restrict__ word,
                                                  const float* __restrict__ Ww,
                                                  const float* __restrict__ Wp) {
    extern __shared__ float sm[];
    uint32_t* smw = (uint32_t*)sm;
    float* Fs   = sm;            // 11840
    float* red  = sm + 11840;    // 2368
    float* Wws  = sm + 17920;    // 6400
    float* Wps  = sm + 24320;    // 1296
    float* cmax = sm + 25616;    // 144
    float* csum = sm + 25760;    // 144

    const int tid  = threadIdx.x;
    const int lane = tid & 31, wid = tid >> 5;
    const int g  = lane >> 2, t4 = lane & 3;
    const int ms = wid >> 1,  ns = wid & 1;        // wid 0..9
    const int b = blockIdx.y, pb = blockIdx.x;

    for (int i = tid; i < 1600; i += 320) ((float4*)Wws)[i] = ((const float4*)Ww)[i];
    for (int i = tid; i < 324;  i += 320) ((float4*)Wps)[i] = ((const float4*)Wp)[i];

    const float* Aw = word + (size_t)b * NW * DIM;
    const float* Bp = g_pl + (size_t)pb * NT * DIM;   // 144 contiguous rows

    float4 pa[2], pb4[4];
#pragma unroll
    for (int j = 0; j < 2; j++) {
        const int pos = tid + 320 * j;                 // < 640
        pa[j] = *(const float4*)&Aw[(pos >> 3) * DIM + 4 * (pos & 7)];
    }
#pragma unroll
    for (int j = 0; j < 4; j++) {
        const int pos = tid + 320 * j;
        if (pos < 1152)
            pb4[j] = *(const float4*)&Bp[(pos >> 3) * DIM + 4 * (pos & 7)];
    }

    float4 acc[9];
    uint32_t ar0[9], ar1[9];
#pragma unroll
    for (int j = 0; j < 9; j++) {
        acc[j] = make_float4(0.f, 0.f, 0.f, 0.f);
        ar0[j] = 0u; ar1[j] = 0u;
    }

    for (int kc = 0; kc < 24; kc++) {
        __syncthreads();
        uint32_t* Ah = smw + (kc & 1) * SMW_BUF;
        uint32_t* Al = Ah + 1600;
        uint32_t* Bh = Ah + 3200;
        uint32_t* Bl = Ah + 6080;
#pragma unroll
        for (int j = 0; j < 2; j++) {
            const int pos = tid + 320 * j, r = pos >> 3, c4 = pos & 7;
            uint32_t hp[2], lp[2];
            split4_f16s(pa[j], hp, lp);
            *(uint2*)&Ah[r * PRS + 2 * c4] = make_uint2(hp[0], hp[1]);
            *(uint2*)&Al[r * PRS + 2 * c4] = make_uint2(lp[0], lp[1]);
        }
#pragma unroll
        for (int j = 0; j < 4; j++) {
            const int pos = tid + 320 * j;
            if (pos < 1152) {
                const int r = pos >> 3, c4 = pos & 7;
                uint32_t hp[2], lp[2];
                split4_f16s(pb4[j], hp, lp);
                *(uint2*)&Bh[r * PRS + 2 * c4] = make_uint2(hp[0], hp[1]);
                *(uint2*)&Bl[r * PRS + 2 * c4] = make_uint2(lp[0], lp[1]);
            }
        }
        __syncthreads();
        if (kc < 23) {
            const int kn = (kc + 1) * 32;
#pragma unroll
            for (int j = 0; j < 2; j++) {
                const int pos = tid + 320 * j;
                pa[j] = *(const float4*)&Aw[(pos >> 3) * DIM + kn + 4 * (pos & 7)];
            }
#pragma unroll
            for (int j = 0; j < 4; j++) {
                const int pos = tid + 320 * j;
                if (pos < 1152)
                    pb4[j] = *(const float4*)&Bp[(pos >> 3) * DIM + kn + 4 * (pos & 7)];
            }
        }
#pragma unroll
        for (int ks = 0; ks < 2; ks++) {
            const int arow = (16 * ms + g) * PRS + ks * 8 + t4;
            const uint32_t ah0 = Ah[arow];
            const uint32_t ah1 = Ah[arow + 8 * PRS];
            const uint32_t ah2 = Ah[arow + 4];
            const uint32_t ah3 = Ah[arow + 8 * PRS + 4];
            const uint32_t al0 = Al[arow];
            const uint32_t al1 = Al[arow + 8 * PRS];
            const uint32_t al2 = Al[arow + 4];
            const uint32_t al3 = Al[arow + 8 * PRS + 4];
#pragma unroll
            for (int nt = 0; nt < 9; nt++) {
                const int brow = (72 * ns + 8 * nt + g) * PRS + ks * 8 + t4;
                const uint32_t bh0 = Bh[brow];
                const uint32_t bh1 = Bh[brow + 4];
                const uint32_t bl0 = Bl[brow];
                const uint32_t bl1 = Bl[brow + 4];
                mma_f16(acc[nt], ah0, ah1, ah2, ah3, bh0, bh1);      // hh (f32 acc)
                mma_f16h(ar0[nt], ar1[nt], ah0, ah1, ah2, ah3, bl0, bl1); // hl (f16 acc)
                mma_f16h(ar0[nt], ar1[nt], al0, al1, al2, al3, bh0, bh1); // lh (f16 acc)
            }
        }
    }
    __syncthreads();

    // F = hh + cross/2048 ; C fragment layout rows g/g+8, cols 2t4, 2t4+1
    const float inv2048 = 1.0f / 2048.0f;
#pragma unroll
    for (int nt = 0; nt < 9; nt++) {
        const int row = 16 * ms + g, col = 72 * ns + 8 * nt + 2 * t4;
        float2 c0 = __half22float2(*reinterpret_cast<__half2*>(&ar0[nt]));
        float2 c1 = __half22float2(*reinterpret_cast<__half2*>(&ar1[nt]));
        Fs[row * FS + col]           = acc[nt].x + c0.x * inv2048;
        Fs[row * FS + col + 1]       = acc[nt].y + c0.y * inv2048;
        Fs[(row + 8) * FS + col]     = acc[nt].z + c1.x * inv2048;
        Fs[(row + 8) * FS + col + 1] = acc[nt].w + c1.y * inv2048;
    }
    __syncthreads();

    if (tid < NT) {
        float m = -1e30f;
        for (int w = 0; w < NW; w++) m = fmaxf(m, Fs[w * FS + tid]);
        float s = 0.0f;
        for (int w = 0; w < NW; w++) s += __expf((Fs[w * FS + tid] - m) * TAU_INV);
        cmax[tid] = m;
        csum[tid] = s;
    }
    float ga[5][9];
    if (tid < 256) {
        const int tx = tid & 15, ty = tid >> 4;
#pragma unroll
        for (int i = 0; i < 5; i++)
#pragma unroll
            for (int j = 0; j < 9; j++) ga[i][j] = 0.0f;
        for (int v4 = 0; v4 < 20; v4++) {
            float aa[5][4];
#pragma unroll
            for (int i = 0; i < 5; i++) {
                float4 a4 = *(float4*)&Wws[(ty + 16 * i) * 80 + 4 * v4];
                aa[i][0] = a4.x; aa[i][1] = a4.y; aa[i][2] = a4.z; aa[i][3] = a4.w;
            }
#pragma unroll
            for (int vv = 0; vv < 4; vv++) {
                const int v = 4 * v4 + vv;
                float bv[9];
#pragma unroll
                for (int j = 0; j < 9; j++) bv[j] = Fs[v * FS + tx + 16 * j];
#pragma unroll
                for (int i = 0; i < 5; i++)
#pragma unroll
                    for (int j = 0; j < 9; j++) ga[i][j] += aa[i][vv] * bv[j];
            }
        }
    }
    __syncthreads();

    if (tid < 256) {
        const int tx = tid & 15, ty = tid >> 4;
#pragma unroll
        for (int j = 0; j < 9; j++) {
            const int c = tx + 16 * j;
            const float m = cmax[c];
            float part = 0.0f;
#pragma unroll
            for (int i = 0; i < 5; i++)
                part += __expf((Fs[(ty + 16 * i) * FS + c] - m) * TAU_INV) * ga[i][j];
            red[ty * FS + c] = part;
        }
    }
    __syncthreads();

    if (tid < NT) {
        float a = 0.0f;
#pragma unroll
        for (int t = 0; t < 16; t++) a += red[t * FS + tid];
        g_wl[(size_t)b * (NP * NQ) + pb * NT + tid] = a / csum[tid];
    }

    for (int pr = tid; pr < NW * PT; pr += 320) {
        const int w = pr >> 2, p = pr & 3;
        const float* frow = &Fs[w * FS + p * NQ];
        float fr[NQ];
#pragma unroll
        for (int c = 0; c < 9; c++) *(float4*)&fr[4 * c] = *(const float4*)&frow[4 * c];
        float m = fr[0];
#pragma unroll
        for (int q = 1; q < NQ; q++) m = fmaxf(m, fr[q]);
        float s = 0.0f, a = 0.0f;
        for (int q = 0; q < NQ; q++) {
            float u = 0.0f;
#pragma unroll
            for (int rv = 0; rv < 9; rv++) {
                float4 w4 = *(float4*)&Wps[q * NQ + 4 * rv];
                u += w4.x * fr[4 * rv] + w4.y * fr[4 * rv + 1] +
                     w4.z * fr[4 * rv + 2] + w4.w * fr[4 * rv + 3];
            }
            const float e = __expf((fr[q] - m) * TAU_INV);
            s += e;
            a += e * u;
        }
        g_plv[(size_t)b * (NW * NP) + w * NP + pb * PT + p] = a / s;
    }
}

// ---------------------------------------------------------------------------
// K3: per b: s2p/p2w second-level reductions -> sim[b][p]
// ---------------------------------------------------------------------------
__global__ void __launch_bounds__(128) k3_stage2(const float* __restrict__ Ww2,
                                                 const float* __restrict__ Wp2) {
    extern __shared__ float sm[];
    float* wls = sm;            // 4608
    float* pls = sm + 4608;     // 10240
    float* W2s = sm + 14848;    // 6400
    float* P2s = sm + 21248;    // 1296
    const int b = blockIdx.x, tid = threadIdx.x;

    const float4* s1 = (const float4*)(g_wl + (size_t)b * (NP * NQ));
    for (int i = tid; i < 1152; i += 128) ((float4*)wls)[i] = s1[i];
    const float4* s2 = (const float4*)(g_plv + (size_t)b * (NW * NP));
    for (int i = tid; i < 2560; i += 128) ((float4*)pls)[i] = s2[i];
    for (int i = tid; i < 1600; i += 128) ((float4*)W2s)[i] = ((const float4*)Ww2)[i];
    for (int i = tid; i < 324;  i += 128) ((float4*)P2s)[i] = ((const float4*)Wp2)[i];
    __syncthreads();

    const int p = tid;
    float fr[NQ];
#pragma unroll
    for (int c = 0; c < 9; c++) *(float4*)&fr[4 * c] = *(float4*)&wls[p * NQ + 4 * c];
    float m = fr[0];
#pragma unroll
    for (int q = 1; q < NQ; q++) m = fmaxf(m, fr[q]);
    float s = 0.0f, a = 0.0f;
    for (int q = 0; q < NQ; q++) {
        float u = 0.0f;
#pragma unroll
        for (int rv = 0; rv < 9; rv++) {
            float4 w4 = *(float4*)&P2s[q * NQ + 4 * rv];
            u += w4.x * fr[4 * rv] + w4.y * fr[4 * rv + 1] +
                 w4.z * fr[4 * rv + 2] + w4.w * fr[4 * rv + 3];
        }
        const float e = __expf((fr[q] - m) * TAU_INV);
        s += e; a += e * u;
    }
    const float s2p = a / s;

    float fw[NW];
    for (int w = 0; w < NW; w++) fw[w] = pls[w * NP + p];
    m = fw[0];
#pragma unroll
    for (int w = 1; w < NW; w++) m = fmaxf(m, fw[w]);
    s = 0.0f; a = 0.0f;
    for (int w = 0; w < NW; w++) {
        float u = 0.0f;
#pragma unroll
        for (int v4 = 0; v4 < 20; v4++) {
            float4 w4 = *(float4*)&W2s[w * NW + 4 * v4];
            u += w4.x * fw[4 * v4] + w4.y * fw[4 * v4 + 1] +
                 w4.z * fw[4 * v4 + 2] + w4.w * fw[4 * v4 + 3];
        }
        const float e = __expf((fw[w] - m) * TAU_INV);
        s += e; a += e * u;
    }
    const float p2w = a / s;

    g_sim[b * NP + p] = 0.5f * (s2p + p2w);
}

// ---------------------------------------------------------------------------
// K4 v2: 256 threads — row-LSE and col-LSE computed concurrently.
// ---------------------------------------------------------------------------
__global__ void __launch_bounds__(256) k4_loss(float* __restrict__ out) {
    extern __shared__ float sm[];
    float* sims = sm;                   // 128*129 (padded)
    float* lse  = sm + 128 * 129;       // 256
    float* red  = sm + 128 * 129 + 256; // 128
    const int tid = threadIdx.x;
    for (int i = tid; i < BS * NP; i += 256) {
        const int r = i >> 7, c = i & 127;
        sims[r * 129 + c] = g_sim[i];
    }
    __syncthreads();
    const int i = tid & 127;
    if (tid < 128) {
        float m = -1e30f;
        for (int j = 0; j < 128; j++) m = fmaxf(m, sims[i * 129 + j]);
        float s = 0.0f;
        for (int j = 0; j < 128; j++) s += expf(sims[i * 129 + j] - m);
        lse[i] = m + logf(s);
    } else {
        float m = -1e30f;
        for (int j = 0; j < 128; j++) m = fmaxf(m, sims[j * 129 + i]);
        float s = 0.0f;
        for (int j = 0; j < 128; j++) s += expf(sims[j * 129 + i] - m);
        lse[128 + i] = m + logf(s);
    }
    __syncthreads();
    if (tid < 128)
        red[i] = sims[i * 129 + i] - 0.5f * (lse[i] + lse[128 + i]);
    __syncthreads();
    for (int st = 64; st > 0; st >>= 1) {
        if (tid < st) red[tid] += red[tid + st];
        __syncthreads();
    }
    if (tid == 0) out[0] = -red[0] / 128.0f;
}

// ---------------------------------------------------------------------------
extern "C" void kernel_launch(void* const* d_in, const int* in_sizes, int n_in,
                              void* d_out, int out_size) {
    const float* patch = (const float*)d_in[0];  // (128, 36, 768)
    const float* word  = (const float*)d_in[1];  // (128, 80, 768)
    const float* L     = (const float*)d_in[2];  // (768, 768)
    const float* Ww    = (const float*)d_in[3];  // (80, 80)
    const float* Wp    = (const float*)d_in[4];  // (36, 36)
    const float* Ww2   = (const float*)d_in[5];  // (80, 80)
    const float* Wp2   = (const float*)d_in[6];  // (36, 36)
    float* out = (float*)d_out;

    const int smem_k1 = 10752 * 4;
    const int smem_k2 = 25904 * 4;
    const int smem_k3 = 22544 * 4;
    const int smem_k4 = (128 * 129 + 256 + 128) * 4;
    cudaFuncSetAttribute(k1_plgemm, cudaFuncAttributeMaxDynamicSharedMemorySize, smem_k1);
    cudaFuncSetAttribute(k2_fine,   cudaFuncAttributeMaxDynamicSharedMemorySize, smem_k2);
    cudaFuncSetAttribute(k3_stage2, cudaFuncAttributeMaxDynamicSharedMemorySize, smem_k3);
    cudaFuncSetAttribute(k4_loss,   cudaFuncAttributeMaxDynamicSharedMemorySize, smem_k4);

    k1_plgemm<<<dim3(8, 36), 256, smem_k1>>>(patch, L);
    k2_fine<<<dim3(NP / PT, BS), 320, smem_k2>>>(word, Ww, Wp);
    k3_stage2<<<BS, 128, smem_k3>>>(Ww2, Wp2);
    k4_loss<<<1, 256, smem_k4>>>(out);
}

// round 10
// speedup vs baseline: 1.2892x; 1.2892x over previous
#include <cuda_runtime.h>
#include <cuda_bf16.h>
#include <cuda_fp16.h>
#include <math.h>
#include <stdint.h>

// Problem constants
#define BS   128
#define NW   80
#define NP   128
#define NQ   36
#define DIM  768
#define TAU_INV 100.0f

#define PT   4            // patches per K2 block
#define NT   144          // PT*NQ columns per tile
#define FS   148          // F row stride in smem

// Scratch (device globals: no allocation allowed)
__device__ float g_pl [NP*NQ*DIM];    // 4608 x 768  : patch @ L^T
__device__ float g_wl [BS*NP*NQ];     // word_level [b][p][q]
__device__ float g_plv[BS*NW*NP];     // patch_level [b][w][p]
__device__ float g_sim[BS*NP];        // sim [b][p]

// ---------------------------------------------------------------------------
// split helpers
// ---------------------------------------------------------------------------
__device__ __forceinline__ uint32_t pack_f16(float lo_elem, float hi_elem) {
    uint32_t r;
    asm("cvt.rn.f16x2.f32 %0, %1, %2;" : "=r"(r) : "f"(hi_elem), "f"(lo_elem));
    return r;
}
__device__ __forceinline__ void split4_f16(float4 v, uint32_t* hp, uint32_t* lp) {
    float h0 = __half2float(__float2half_rn(v.x));
    float h1 = __half2float(__float2half_rn(v.y));
    float h2 = __half2float(__float2half_rn(v.z));
    float h3 = __half2float(__float2half_rn(v.w));
    hp[0] = pack_f16(h0, h1);
    hp[1] = pack_f16(h2, h3);
    lp[0] = pack_f16(v.x - h0, v.y - h1);
    lp[1] = pack_f16(v.z - h2, v.w - h3);
}
// hi-only pack (for the B operand whose residual product is dropped)
__device__ __forceinline__ void pack4hi_f16(float4 v, uint32_t* hp) {
    hp[0] = pack_f16(v.x, v.y);
    hp[1] = pack_f16(v.z, v.w);
}
__device__ __forceinline__ void mma_f16(float4& d,
    uint32_t a0, uint32_t a1, uint32_t a2, uint32_t a3,
    uint32_t b0, uint32_t b1) {
    asm volatile(
        "mma.sync.aligned.m16n8k16.row.col.f32.f16.f16.f32 "
        "{%0,%1,%2,%3}, {%4,%5,%6,%7}, {%8,%9}, {%0,%1,%2,%3};\n"
        : "+f"(d.x), "+f"(d.y), "+f"(d.z), "+f"(d.w)
        : "r"(a0), "r"(a1), "r"(a2), "r"(a3), "r"(b0), "r"(b1));
}

// ---------------------------------------------------------------------------
// K1 v2: pl = patch2d @ L^T via fp16 2-split mma (3 products, f32 acc).
// (unchanged from R8)
// ---------------------------------------------------------------------------
#define K1PRS 12
#define K1_STG 5376

__global__ void __launch_bounds__(256, 2) k1_plgemm(const float* __restrict__ patch,
                                                    const float* __restrict__ L) {
    extern __shared__ float smf[];
    uint32_t* smw = (uint32_t*)smf;
    const int tid = threadIdx.x;
    const int lane = tid & 31, wid = tid >> 5;
    const int g = lane >> 2, t4 = lane & 3;
    const int mw = wid >> 1, nw = wid & 1;
    const int m0 = blockIdx.y * 128;
    const int n0 = blockIdx.x * 96;
    const float* Ap = patch + (size_t)m0 * DIM;
    const float* Bp = L + (size_t)n0 * DIM;

    float4 pa[2], pb[2];
#pragma unroll
    for (int j = 0; j < 2; j++) {
        const int pos = tid + 256 * j;
        pa[j] = *(const float4*)&Ap[(pos >> 2) * DIM + 4 * (pos & 3)];
    }
#pragma unroll
    for (int j = 0; j < 2; j++) {
        const int pos = tid + 256 * j;
        if (pos < 384)
            pb[j] = *(const float4*)&Bp[(pos >> 2) * DIM + 4 * (pos & 3)];
    }

    float4 acc[2][6];
#pragma unroll
    for (int i = 0; i < 2; i++)
#pragma unroll
        for (int j = 0; j < 6; j++) acc[i][j] = make_float4(0.f, 0.f, 0.f, 0.f);

    for (int kc = 0; kc < 48; kc++) {
        __syncthreads();
        uint32_t* Ah = smw + (kc & 1) * K1_STG;
        uint32_t* Al = Ah + 1536;
        uint32_t* Bh = Ah + 3072;
        uint32_t* Bl = Ah + 4224;
#pragma unroll
        for (int j = 0; j < 2; j++) {
            const int pos = tid + 256 * j, r = pos >> 2, c4 = pos & 3;
            uint32_t hp[2], lp[2];
            split4_f16(pa[j], hp, lp);
            *(uint2*)&Ah[r * K1PRS + 2 * c4] = make_uint2(hp[0], hp[1]);
            *(uint2*)&Al[r * K1PRS + 2 * c4] = make_uint2(lp[0], lp[1]);
        }
#pragma unroll
        for (int j = 0; j < 2; j++) {
            const int pos = tid + 256 * j;
            if (pos < 384) {
                const int r = pos >> 2, c4 = pos & 3;
                uint32_t hp[2], lp[2];
                split4_f16(pb[j], hp, lp);
                *(uint2*)&Bh[r * K1PRS + 2 * c4] = make_uint2(hp[0], hp[1]);
                *(uint2*)&Bl[r * K1PRS + 2 * c4] = make_uint2(lp[0], lp[1]);
            }
        }
        __syncthreads();
        if (kc < 47) {
            const int kn = (kc + 1) * 16;
#pragma unroll
            for (int j = 0; j < 2; j++) {
                const int pos = tid + 256 * j;
                pa[j] = *(const float4*)&Ap[(pos >> 2) * DIM + kn + 4 * (pos & 3)];
            }
#pragma unroll
            for (int j = 0; j < 2; j++) {
                const int pos = tid + 256 * j;
                if (pos < 384)
                    pb[j] = *(const float4*)&Bp[(pos >> 2) * DIM + kn + 4 * (pos & 3)];
            }
        }
#pragma unroll
        for (int mt = 0; mt < 2; mt++) {
            const int arow = (mw * 32 + mt * 16 + g) * K1PRS + t4;
            const uint32_t ah0 = Ah[arow];
            const uint32_t ah1 = Ah[arow + 8 * K1PRS];
            const uint32_t ah2 = Ah[arow + 4];
            const uint32_t ah3 = Ah[arow + 8 * K1PRS + 4];
            const uint32_t al0 = Al[arow];
            const uint32_t al1 = Al[arow + 8 * K1PRS];
            const uint32_t al2 = Al[arow + 4];
            const uint32_t al3 = Al[arow + 8 * K1PRS + 4];
#pragma unroll
            for (int nt = 0; nt < 6; nt++) {
                const int brow = (nw * 48 + nt * 8 + g) * K1PRS + t4;
                const uint32_t bh0 = Bh[brow];
                const uint32_t bh1 = Bh[brow + 4];
                const uint32_t bl0 = Bl[brow];
                const uint32_t bl1 = Bl[brow + 4];
                mma_f16(acc[mt][nt], ah0, ah1, ah2, ah3, bh0, bh1);
                mma_f16(acc[mt][nt], ah0, ah1, ah2, ah3, bl0, bl1);
                mma_f16(acc[mt][nt], al0, al1, al2, al3, bh0, bh1);
            }
        }
    }

#pragma unroll
    for (int mt = 0; mt < 2; mt++) {
#pragma unroll
        for (int nt = 0; nt < 6; nt++) {
            const int row = m0 + mw * 32 + mt * 16 + g;
            const int col = n0 + nw * 48 + nt * 8 + 2 * t4;
            g_pl[(size_t)row * DIM + col]           = acc[mt][nt].x;
            g_pl[(size_t)row * DIM + col + 1]       = acc[mt][nt].y;
            g_pl[(size_t)(row + 8) * DIM + col]     = acc[mt][nt].z;
            g_pl[(size_t)(row + 8) * DIM + col + 1] = acc[mt][nt].w;
        }
    }
}

// ---------------------------------------------------------------------------
// K2 v7: fp16 split, 2 products (hh + lh; a_hi*b_lo dropped), f32 acc.
//   F[80][144] = word[b] @ pl[ptile]^T
// smem (words): per stage Ah 1600 | Al 1600 | Bh 2880 = 6080; x2 = 12160
// epilogue: Fs@0 (11840), red@11840 (2368) -> 14208
// weights: Wws@14208 (6400), Wps@20608 (1296), cmax@21904, csum@22048
// total 22192 floats = 88768 B  -> 2 CTAs/SM
// ---------------------------------------------------------------------------
#define SMW_BUF 6080
#define PRS 20          // pair-row stride in words

__global__ void __launch_bounds__(320, 2) k2_fine(const float* __restrict__ word,
                                                  const float* __restrict__ Ww,
                                                  const float* __restrict__ Wp) {
    extern __shared__ float sm[];
    uint32_t* smw = (uint32_t*)sm;
    float* Fs   = sm;            // 11840
    float* red  = sm + 11840;    // 2368
    float* Wws  = sm + 14208;    // 6400
    float* Wps  = sm + 20608;    // 1296
    float* cmax = sm + 21904;    // 144
    float* csum = sm + 22048;    // 144

    const int tid  = threadIdx.x;
    const int lane = tid & 31, wid = tid >> 5;
    const int g  = lane >> 2, t4 = lane & 3;
    const int ms = wid >> 1,  ns = wid & 1;        // wid 0..9
    const int b = blockIdx.y, pb = blockIdx.x;

    for (int i = tid; i < 1600; i += 320) ((float4*)Wws)[i] = ((const float4*)Ww)[i];
    for (int i = tid; i < 324;  i += 320) ((float4*)Wps)[i] = ((const float4*)Wp)[i];

    const float* Aw = word + (size_t)b * NW * DIM;
    const float* Bp = g_pl + (size_t)pb * NT * DIM;   // 144 contiguous rows

    float4 pa[2], pb4[4];
#pragma unroll
    for (int j = 0; j < 2; j++) {
        const int pos = tid + 320 * j;                 // < 640
        pa[j] = *(const float4*)&Aw[(pos >> 3) * DIM + 4 * (pos & 7)];
    }
#pragma unroll
    for (int j = 0; j < 4; j++) {
        const int pos = tid + 320 * j;
        if (pos < 1152)
            pb4[j] = *(const float4*)&Bp[(pos >> 3) * DIM + 4 * (pos & 7)];
    }

    float4 acc[9];
#pragma unroll
    for (int j = 0; j < 9; j++) acc[j] = make_float4(0.f, 0.f, 0.f, 0.f);

    for (int kc = 0; kc < 24; kc++) {
        __syncthreads();
        uint32_t* Ah = smw + (kc & 1) * SMW_BUF;
        uint32_t* Al = Ah + 1600;
        uint32_t* Bh = Ah + 3200;
#pragma unroll
        for (int j = 0; j < 2; j++) {
            const int pos = tid + 320 * j, r = pos >> 3, c4 = pos & 7;
            uint32_t hp[2], lp[2];
            split4_f16(pa[j], hp, lp);
            *(uint2*)&Ah[r * PRS + 2 * c4] = make_uint2(hp[0], hp[1]);
            *(uint2*)&Al[r * PRS + 2 * c4] = make_uint2(lp[0], lp[1]);
        }
#pragma unroll
        for (int j = 0; j < 4; j++) {
            const int pos = tid + 320 * j;
            if (pos < 1152) {
                const int r = pos >> 3, c4 = pos & 7;
                uint32_t hp[2];
                pack4hi_f16(pb4[j], hp);
                *(uint2*)&Bh[r * PRS + 2 * c4] = make_uint2(hp[0], hp[1]);
            }
        }
        __syncthreads();
        if (kc < 23) {
            const int kn = (kc + 1) * 32;
#pragma unroll
            for (int j = 0; j < 2; j++) {
                const int pos = tid + 320 * j;
                pa[j] = *(const float4*)&Aw[(pos >> 3) * DIM + kn + 4 * (pos & 7)];
            }
#pragma unroll
            for (int j = 0; j < 4; j++) {
                const int pos = tid + 320 * j;
                if (pos < 1152)
                    pb4[j] = *(const float4*)&Bp[(pos >> 3) * DIM + kn + 4 * (pos & 7)];
            }
        }
#pragma unroll
        for (int ks = 0; ks < 2; ks++) {
            const int arow = (16 * ms + g) * PRS + ks * 8 + t4;
            const uint32_t ah0 = Ah[arow];
            const uint32_t ah1 = Ah[arow + 8 * PRS];
            const uint32_t ah2 = Ah[arow + 4];
            const uint32_t ah3 = Ah[arow + 8 * PRS + 4];
            const uint32_t al0 = Al[arow];
            const uint32_t al1 = Al[arow + 8 * PRS];
            const uint32_t al2 = Al[arow + 4];
            const uint32_t al3 = Al[arow + 8 * PRS + 4];
#pragma unroll
            for (int nt = 0; nt < 9; nt++) {
                const int brow = (72 * ns + 8 * nt + g) * PRS + ks * 8 + t4;
                const uint32_t bh0 = Bh[brow];
                const uint32_t bh1 = Bh[brow + 4];
                mma_f16(acc[nt], ah0, ah1, ah2, ah3, bh0, bh1);   // hh
                mma_f16(acc[nt], al0, al1, al2, al3, bh0, bh1);   // lh
            }
        }
    }
    __syncthreads();

    // F tile -> smem (C fragment layout: rows g/g+8, cols 2t4, 2t4+1)
#pragma unroll
    for (int nt = 0; nt < 9; nt++) {
        const int row = 16 * ms + g, col = 72 * ns + 8 * nt + 2 * t4;
        Fs[row * FS + col]           = acc[nt].x;
        Fs[row * FS + col + 1]       = acc[nt].y;
        Fs[(row + 8) * FS + col]     = acc[nt].z;
        Fs[(row + 8) * FS + col + 1] = acc[nt].w;
    }
    __syncthreads();

    if (tid < NT) {
        float m = -1e30f;
        for (int w = 0; w < NW; w++) m = fmaxf(m, Fs[w * FS + tid]);
        float s = 0.0f;
        for (int w = 0; w < NW; w++) s += __expf((Fs[w * FS + tid] - m) * TAU_INV);
        cmax[tid] = m;
        csum[tid] = s;
    }
    float ga[5][9];
    if (tid < 256) {
        const int tx = tid & 15, ty = tid >> 4;
#pragma unroll
        for (int i = 0; i < 5; i++)
#pragma unroll
            for (int j = 0; j < 9; j++) ga[i][j] = 0.0f;
        for (int v4 = 0; v4 < 20; v4++) {
            float aa[5][4];
#pragma unroll
            for (int i = 0; i < 5; i++) {
                float4 a4 = *(float4*)&Wws[(ty + 16 * i) * 80 + 4 * v4];
                aa[i][0] = a4.x; aa[i][1] = a4.y; aa[i][2] = a4.z; aa[i][3] = a4.w;
            }
#pragma unroll
            for (int vv = 0; vv < 4; vv++) {
                const int v = 4 * v4 + vv;
                float bv[9];
#pragma unroll
                for (int j = 0; j < 9; j++) bv[j] = Fs[v * FS + tx + 16 * j];
#pragma unroll
                for (int i = 0; i < 5; i++)
#pragma unroll
                    for (int j = 0; j < 9; j++) ga[i][j] += aa[i][vv] * bv[j];
            }
        }
    }
    __syncthreads();

    if (tid < 256) {
        const int tx = tid & 15, ty = tid >> 4;
#pragma unroll
        for (int j = 0; j < 9; j++) {
            const int c = tx + 16 * j;
            const float m = cmax[c];
            float part = 0.0f;
#pragma unroll
            for (int i = 0; i < 5; i++)
                part += __expf((Fs[(ty + 16 * i) * FS + c] - m) * TAU_INV) * ga[i][j];
            red[ty * FS + c] = part;
        }
    }
    __syncthreads();

    if (tid < NT) {
        float a = 0.0f;
#pragma unroll
        for (int t = 0; t < 16; t++) a += red[t * FS + tid];
        g_wl[(size_t)b * (NP * NQ) + pb * NT + tid] = a / csum[tid];
    }

    for (int pr = tid; pr < NW * PT; pr += 320) {
        const int w = pr >> 2, p = pr & 3;
        const float* frow = &Fs[w * FS + p * NQ];
        float fr[NQ];
#pragma unroll
        for (int c = 0; c < 9; c++) *(float4*)&fr[4 * c] = *(const float4*)&frow[4 * c];
        float m = fr[0];
#pragma unroll
        for (int q = 1; q < NQ; q++) m = fmaxf(m, fr[q]);
        float s = 0.0f, a = 0.0f;
        for (int q = 0; q < NQ; q++) {
            float u = 0.0f;
#pragma unroll
            for (int rv = 0; rv < 9; rv++) {
                float4 w4 = *(float4*)&Wps[q * NQ + 4 * rv];
                u += w4.x * fr[4 * rv] + w4.y * fr[4 * rv + 1] +
                     w4.z * fr[4 * rv + 2] + w4.w * fr[4 * rv + 3];
            }
            const float e = __expf((fr[q] - m) * TAU_INV);
            s += e;
            a += e * u;
        }
        g_plv[(size_t)b * (NW * NP) + w * NP + pb * PT + p] = a / s;
    }
}

// ---------------------------------------------------------------------------
// K3: per b: s2p/p2w second-level reductions -> sim[b][p]
// ---------------------------------------------------------------------------
__global__ void __launch_bounds__(128) k3_stage2(const float* __restrict__ Ww2,
                                                 const float* __restrict__ Wp2) {
    extern __shared__ float sm[];
    float* wls = sm;            // 4608
    float* pls = sm + 4608;     // 10240
    float* W2s = sm + 14848;    // 6400
    float* P2s = sm + 21248;    // 1296
    const int b = blockIdx.x, tid = threadIdx.x;

    const float4* s1 = (const float4*)(g_wl + (size_t)b * (NP * NQ));
    for (int i = tid; i < 1152; i += 128) ((float4*)wls)[i] = s1[i];
    const float4* s2 = (const float4*)(g_plv + (size_t)b * (NW * NP));
    for (int i = tid; i < 2560; i += 128) ((float4*)pls)[i] = s2[i];
    for (int i = tid; i < 1600; i += 128) ((float4*)W2s)[i] = ((const float4*)Ww2)[i];
    for (int i = tid; i < 324;  i += 128) ((float4*)P2s)[i] = ((const float4*)Wp2)[i];
    __syncthreads();

    const int p = tid;
    float fr[NQ];
#pragma unroll
    for (int c = 0; c < 9; c++) *(float4*)&fr[4 * c] = *(float4*)&wls[p * NQ + 4 * c];
    float m = fr[0];
#pragma unroll
    for (int q = 1; q < NQ; q++) m = fmaxf(m, fr[q]);
    float s = 0.0f, a = 0.0f;
    for (int q = 0; q < NQ; q++) {
        float u = 0.0f;
#pragma unroll
        for (int rv = 0; rv < 9; rv++) {
            float4 w4 = *(float4*)&P2s[q * NQ + 4 * rv];
            u += w4.x * fr[4 * rv] + w4.y * fr[4 * rv + 1] +
                 w4.z * fr[4 * rv + 2] + w4.w * fr[4 * rv + 3];
        }
        const float e = __expf((fr[q] - m) * TAU_INV);
        s += e; a += e * u;
    }
    const float s2p = a / s;

    float fw[NW];
    for (int w = 0; w < NW; w++) fw[w] = pls[w * NP + p];
    m = fw[0];
#pragma unroll
    for (int w = 1; w < NW; w++) m = fmaxf(m, fw[w]);
    s = 0.0f; a = 0.0f;
    for (int w = 0; w < NW; w++) {
        float u = 0.0f;
#pragma unroll
        for (int v4 = 0; v4 < 20; v4++) {
            float4 w4 = *(float4*)&W2s[w * NW + 4 * v4];
            u += w4.x * fw[4 * v4] + w4.y * fw[4 * v4 + 1] +
                 w4.z * fw[4 * v4 + 2] + w4.w * fw[4 * v4 + 3];
        }
        const float e = __expf((fw[w] - m) * TAU_INV);
        s += e; a += e * u;
    }
    const float p2w = a / s;

    g_sim[b * NP + p] = 0.5f * (s2p + p2w);
}

// ---------------------------------------------------------------------------
// K4 v2: 256 threads — row-LSE and col-LSE computed concurrently.
// ---------------------------------------------------------------------------
__global__ void __launch_bounds__(256) k4_loss(float* __restrict__ out) {
    extern __shared__ float sm[];
    float* sims = sm;                   // 128*129 (padded)
    float* lse  = sm + 128 * 129;       // 256
    float* red  = sm + 128 * 129 + 256; // 128
    const int tid = threadIdx.x;
    for (int i = tid; i < BS * NP; i += 256) {
        const int r = i >> 7, c = i & 127;
        sims[r * 129 + c] = g_sim[i];
    }
    __syncthreads();
    const int i = tid & 127;
    if (tid < 128) {
        float m = -1e30f;
        for (int j = 0; j < 128; j++) m = fmaxf(m, sims[i * 129 + j]);
        float s = 0.0f;
        for (int j = 0; j < 128; j++) s += expf(sims[i * 129 + j] - m);
        lse[i] = m + logf(s);
    } else {
        float m = -1e30f;
        for (int j = 0; j < 128; j++) m = fmaxf(m, sims[j * 129 + i]);
        float s = 0.0f;
        for (int j = 0; j < 128; j++) s += expf(sims[j * 129 + i] - m);
        lse[128 + i] = m + logf(s);
    }
    __syncthreads();
    if (tid < 128)
        red[i] = sims[i * 129 + i] - 0.5f * (lse[i] + lse[128 + i]);
    __syncthreads();
    for (int st = 64; st > 0; st >>= 1) {
        if (tid < st) red[tid] += red[tid + st];
        __syncthreads();
    }
    if (tid == 0) out[0] = -red[0] / 128.0f;
}

// ---------------------------------------------------------------------------
extern "C" void kernel_launch(void* const* d_in, const int* in_sizes, int n_in,
                              void* d_out, int out_size) {
    const float* patch = (const float*)d_in[0];  // (128, 36, 768)
    const float* word  = (const float*)d_in[1];  // (128, 80, 768)
    const float* L     = (const float*)d_in[2];  // (768, 768)
    const float* Ww    = (const float*)d_in[3];  // (80, 80)
    const float* Wp    = (const float*)d_in[4];  // (36, 36)
    const float* Ww2   = (const float*)d_in[5];  // (80, 80)
    const float* Wp2   = (const float*)d_in[6];  // (36, 36)
    float* out = (float*)d_out;

    const int smem_k1 = 10752 * 4;
    const int smem_k2 = 22192 * 4;
    const int smem_k3 = 22544 * 4;
    const int smem_k4 = (128 * 129 + 256 + 128) * 4;
    cudaFuncSetAttribute(k1_plgemm, cudaFuncAttributeMaxDynamicSharedMemorySize, smem_k1);
    cudaFuncSetAttribute(k2_fine,   cudaFuncAttributeMaxDynamicSharedMemorySize, smem_k2);
    cudaFuncSetAttribute(k3_stage2, cudaFuncAttributeMaxDynamicSharedMemorySize, smem_k3);
    cudaFuncSetAttribute(k4_loss,   cudaFuncAttributeMaxDynamicSharedMemorySize, smem_k4);

    k1_plgemm<<<dim3(8, 36), 256, smem_k1>>>(patch, L);
    k2_fine<<<dim3(NP / PT, BS), 320, smem_k2>>>(word, Ww, Wp);
    k3_stage2<<<BS, 128, smem_k3>>>(Ww2, Wp2);
    k4_loss<<<1, 256, smem_k4>>>(out);
}

// round 12
// speedup vs baseline: 1.5535x; 1.2050x over previous
#include <cuda_runtime.h>
#include <cuda_fp16.h>
#include <math.h>
#include <stdint.h>

// Problem constants
#define BS   128
#define NW   80
#define NP   128
#define NQ   36
#define DIM  768
#define TAU_INV 100.0f

#define PT   4            // patches per K2 block
#define NT   144          // PT*NQ columns per tile
#define FS   148          // F row stride in smem

// Scratch (device globals: no allocation allowed)
__device__ float g_pl [NP*NQ*DIM];    // 4608 x 768  : patch @ L^T
__device__ float g_wl [BS*NP*NQ];     // word_level [b][p][q]
__device__ float g_plv[BS*NW*NP];     // patch_level [b][w][p]
__device__ float g_sim[BS*NP];        // sim [b][p]

// ---------------------------------------------------------------------------
// helpers
// ---------------------------------------------------------------------------
__device__ __forceinline__ uint32_t pack_f16(float lo_elem, float hi_elem) {
    uint32_t r;
    asm("cvt.rn.f16x2.f32 %0, %1, %2;" : "=r"(r) : "f"(hi_elem), "f"(lo_elem));
    return r;
}
__device__ __forceinline__ void pack4_f16(float4 v, uint32_t* hp) {
    hp[0] = pack_f16(v.x, v.y);
    hp[1] = pack_f16(v.z, v.w);
}
__device__ __forceinline__ void mma_f16(float4& d,
    uint32_t a0, uint32_t a1, uint32_t a2, uint32_t a3,
    uint32_t b0, uint32_t b1) {
    asm volatile(
        "mma.sync.aligned.m16n8k16.row.col.f32.f16.f16.f32 "
        "{%0,%1,%2,%3}, {%4,%5,%6,%7}, {%8,%9}, {%0,%1,%2,%3};\n"
        : "+f"(d.x), "+f"(d.y), "+f"(d.z), "+f"(d.w)
        : "r"(a0), "r"(a1), "r"(a2), "r"(a3), "r"(b0), "r"(b1));
}

// ---------------------------------------------------------------------------
// K1 v3: pl = patch2d @ L^T, pure fp16 mma (single product, f32 acc).
//   M=4608, N=768, K=768. Tile 128x96, k16 chunks (48), 2-stage.
// smem (words): per stage Ah 128*12=1536 | Bh 96*12=1152 = 2688; x2 = 5376
// ---------------------------------------------------------------------------
#define K1PRS 12
#define K1_STG 2688

__global__ void __launch_bounds__(256, 2) k1_plgemm(const float* __restrict__ patch,
                                                    const float* __restrict__ L) {
    extern __shared__ float smf[];
    uint32_t* smw = (uint32_t*)smf;
    const int tid = threadIdx.x;
    const int lane = tid & 31, wid = tid >> 5;
    const int g = lane >> 2, t4 = lane & 3;
    const int mw = wid >> 1, nw = wid & 1;
    const int m0 = blockIdx.y * 128;
    const int n0 = blockIdx.x * 96;
    const float* Ap = patch + (size_t)m0 * DIM;
    const float* Bp = L + (size_t)n0 * DIM;

    float4 pa[2], pb[2];
#pragma unroll
    for (int j = 0; j < 2; j++) {
        const int pos = tid + 256 * j;
        pa[j] = *(const float4*)&Ap[(pos >> 2) * DIM + 4 * (pos & 3)];
    }
#pragma unroll
    for (int j = 0; j < 2; j++) {
        const int pos = tid + 256 * j;
        if (pos < 384)
            pb[j] = *(const float4*)&Bp[(pos >> 2) * DIM + 4 * (pos & 3)];
    }

    float4 acc[2][6];
#pragma unroll
    for (int i = 0; i < 2; i++)
#pragma unroll
        for (int j = 0; j < 6; j++) acc[i][j] = make_float4(0.f, 0.f, 0.f, 0.f);

    for (int kc = 0; kc < 48; kc++) {
        __syncthreads();
        uint32_t* Ah = smw + (kc & 1) * K1_STG;
        uint32_t* Bh = Ah + 1536;
#pragma unroll
        for (int j = 0; j < 2; j++) {
            const int pos = tid + 256 * j, r = pos >> 2, c4 = pos & 3;
            uint32_t hp[2];
            pack4_f16(pa[j], hp);
            *(uint2*)&Ah[r * K1PRS + 2 * c4] = make_uint2(hp[0], hp[1]);
        }
#pragma unroll
        for (int j = 0; j < 2; j++) {
            const int pos = tid + 256 * j;
            if (pos < 384) {
                const int r = pos >> 2, c4 = pos & 3;
                uint32_t hp[2];
                pack4_f16(pb[j], hp);
                *(uint2*)&Bh[r * K1PRS + 2 * c4] = make_uint2(hp[0], hp[1]);
            }
        }
        __syncthreads();
        if (kc < 47) {
            const int kn = (kc + 1) * 16;
#pragma unroll
            for (int j = 0; j < 2; j++) {
                const int pos = tid + 256 * j;
                pa[j] = *(const float4*)&Ap[(pos >> 2) * DIM + kn + 4 * (pos & 3)];
            }
#pragma unroll
            for (int j = 0; j < 2; j++) {
                const int pos = tid + 256 * j;
                if (pos < 384)
                    pb[j] = *(const float4*)&Bp[(pos >> 2) * DIM + kn + 4 * (pos & 3)];
            }
        }
#pragma unroll
        for (int mt = 0; mt < 2; mt++) {
            const int arow = (mw * 32 + mt * 16 + g) * K1PRS + t4;
            const uint32_t a0 = Ah[arow];
            const uint32_t a1 = Ah[arow + 8 * K1PRS];
            const uint32_t a2 = Ah[arow + 4];
            const uint32_t a3 = Ah[arow + 8 * K1PRS + 4];
#pragma unroll
            for (int nt = 0; nt < 6; nt++) {
                const int brow = (nw * 48 + nt * 8 + g) * K1PRS + t4;
                mma_f16(acc[mt][nt], a0, a1, a2, a3, Bh[brow], Bh[brow + 4]);
            }
        }
    }

#pragma unroll
    for (int mt = 0; mt < 2; mt++) {
#pragma unroll
        for (int nt = 0; nt < 6; nt++) {
            const int row = m0 + mw * 32 + mt * 16 + g;
            const int col = n0 + nw * 48 + nt * 8 + 2 * t4;
            g_pl[(size_t)row * DIM + col]           = acc[mt][nt].x;
            g_pl[(size_t)row * DIM + col + 1]       = acc[mt][nt].y;
            g_pl[(size_t)(row + 8) * DIM + col]     = acc[mt][nt].z;
            g_pl[(size_t)(row + 8) * DIM + col + 1] = acc[mt][nt].w;
        }
    }
}

// ---------------------------------------------------------------------------
// K2 v8: pure fp16 mma (single product, f32 acc), register-G epilogue, 2 CTAs/SM.
//   F[80][144] = word[b] @ pl[ptile]^T
// smem (words): per stage Ah 1600 | Bh 2880 = 4480; x2 = 8960
// epilogue: Fs@0 (11840), red@11840 (2368) -> 14208
// weights: Wws@14208 (6400), Wps@20608 (1296), cmax@21904, csum@22048
// total 22192 floats = 88768 B  -> 2 CTAs/SM
// ---------------------------------------------------------------------------
#define SMW_BUF 4480
#define PRS 20          // pair-row stride in words

__global__ void __launch_bounds__(320, 2) k2_fine(const float* __restrict__ word,
                                                  const float* __restrict__ Ww,
                                                  const float* __restrict__ Wp) {
    extern __shared__ float sm[];
    uint32_t* smw = (uint32_t*)sm;
    float* Fs   = sm;            // 11840
    float* red  = sm + 11840;    // 2368
    float* Wws  = sm + 14208;    // 6400
    float* Wps  = sm + 20608;    // 1296
    float* cmax = sm + 21904;    // 144
    float* csum = sm + 22048;    // 144

    const int tid  = threadIdx.x;
    const int lane = tid & 31, wid = tid >> 5;
    const int g  = lane >> 2, t4 = lane & 3;
    const int ms = wid >> 1,  ns = wid & 1;        // wid 0..9
    const int b = blockIdx.y, pb = blockIdx.x;

    for (int i = tid; i < 1600; i += 320) ((float4*)Wws)[i] = ((const float4*)Ww)[i];
    for (int i = tid; i < 324;  i += 320) ((float4*)Wps)[i] = ((const float4*)Wp)[i];

    const float* Aw = word + (size_t)b * NW * DIM;
    const float* Bp = g_pl + (size_t)pb * NT * DIM;   // 144 contiguous rows

    float4 pa[2], pb4[4];
#pragma unroll
    for (int j = 0; j < 2; j++) {
        const int pos = tid + 320 * j;                 // < 640
        pa[j] = *(const float4*)&Aw[(pos >> 3) * DIM + 4 * (pos & 7)];
    }
#pragma unroll
    for (int j = 0; j < 4; j++) {
        const int pos = tid + 320 * j;
        if (pos < 1152)
            pb4[j] = *(const float4*)&Bp[(pos >> 3) * DIM + 4 * (pos & 7)];
    }

    float4 acc[9];
#pragma unroll
    for (int j = 0; j < 9; j++) acc[j] = make_float4(0.f, 0.f, 0.f, 0.f);

    for (int kc = 0; kc < 24; kc++) {
        __syncthreads();
        uint32_t* Ah = smw + (kc & 1) * SMW_BUF;
        uint32_t* Bh = Ah + 1600;
#pragma unroll
        for (int j = 0; j < 2; j++) {
            const int pos = tid + 320 * j, r = pos >> 3, c4 = pos & 7;
            uint32_t hp[2];
            pack4_f16(pa[j], hp);
            *(uint2*)&Ah[r * PRS + 2 * c4] = make_uint2(hp[0], hp[1]);
        }
#pragma unroll
        for (int j = 0; j < 4; j++) {
            const int pos = tid + 320 * j;
            if (pos < 1152) {
                const int r = pos >> 3, c4 = pos & 7;
                uint32_t hp[2];
                pack4_f16(pb4[j], hp);
                *(uint2*)&Bh[r * PRS + 2 * c4] = make_uint2(hp[0], hp[1]);
            }
        }
        __syncthreads();
        if (kc < 23) {
            const int kn = (kc + 1) * 32;
#pragma unroll
            for (int j = 0; j < 2; j++) {
                const int pos = tid + 320 * j;
                pa[j] = *(const float4*)&Aw[(pos >> 3) * DIM + kn + 4 * (pos & 7)];
            }
#pragma unroll
            for (int j = 0; j < 4; j++) {
                const int pos = tid + 320 * j;
                if (pos < 1152)
                    pb4[j] = *(const float4*)&Bp[(pos >> 3) * DIM + kn + 4 * (pos & 7)];
            }
        }
#pragma unroll
        for (int ks = 0; ks < 2; ks++) {
            const int arow = (16 * ms + g) * PRS + ks * 8 + t4;
            const uint32_t a0 = Ah[arow];
            const uint32_t a1 = Ah[arow + 8 * PRS];
            const uint32_t a2 = Ah[arow + 4];
            const uint32_t a3 = Ah[arow + 8 * PRS + 4];
#pragma unroll
            for (int nt = 0; nt < 9; nt++) {
                const int brow = (72 * ns + 8 * nt + g) * PRS + ks * 8 + t4;
                mma_f16(acc[nt], a0, a1, a2, a3, Bh[brow], Bh[brow + 4]);
            }
        }
    }
    __syncthreads();

    // F tile -> smem (C fragment layout: rows g/g+8, cols 2t4, 2t4+1)
#pragma unroll
    for (int nt = 0; nt < 9; nt++) {
        const int row = 16 * ms + g, col = 72 * ns + 8 * nt + 2 * t4;
        Fs[row * FS + col]           = acc[nt].x;
        Fs[row * FS + col + 1]       = acc[nt].y;
        Fs[(row + 8) * FS + col]     = acc[nt].z;
        Fs[(row + 8) * FS + col + 1] = acc[nt].w;
    }
    __syncthreads();

    if (tid < NT) {
        float m = -1e30f;
        for (int w = 0; w < NW; w++) m = fmaxf(m, Fs[w * FS + tid]);
        float s = 0.0f;
        for (int w = 0; w < NW; w++) s += __expf((Fs[w * FS + tid] - m) * TAU_INV);
        cmax[tid] = m;
        csum[tid] = s;
    }
    float ga[5][9];
    if (tid < 256) {
        const int tx = tid & 15, ty = tid >> 4;
#pragma unroll
        for (int i = 0; i < 5; i++)
#pragma unroll
            for (int j = 0; j < 9; j++) ga[i][j] = 0.0f;
        for (int v4 = 0; v4 < 20; v4++) {
            float aa[5][4];
#pragma unroll
            for (int i = 0; i < 5; i++) {
                float4 a4 = *(float4*)&Wws[(ty + 16 * i) * 80 + 4 * v4];
                aa[i][0] = a4.x; aa[i][1] = a4.y; aa[i][2] = a4.z; aa[i][3] = a4.w;
            }
#pragma unroll
            for (int vv = 0; vv < 4; vv++) {
                const int v = 4 * v4 + vv;
                float bv[9];
#pragma unroll
                for (int j = 0; j < 9; j++) bv[j] = Fs[v * FS + tx + 16 * j];
#pragma unroll
                for (int i = 0; i < 5; i++)
#pragma unroll
                    for (int j = 0; j < 9; j++) ga[i][j] += aa[i][vv] * bv[j];
            }
        }
    }
    __syncthreads();

    if (tid < 256) {
        const int tx = tid & 15, ty = tid >> 4;
#pragma unroll
        for (int j = 0; j < 9; j++) {
            const int c = tx + 16 * j;
            const float m = cmax[c];
            float part = 0.0f;
#pragma unroll
            for (int i = 0; i < 5; i++)
                part += __expf((Fs[(ty + 16 * i) * FS + c] - m) * TAU_INV) * ga[i][j];
            red[ty * FS + c] = part;
        }
    }
    __syncthreads();

    if (tid < NT) {
        float a = 0.0f;
#pragma unroll
        for (int t = 0; t < 16; t++) a += red[t * FS + tid];
        g_wl[(size_t)b * (NP * NQ) + pb * NT + tid] = a / csum[tid];
    }

    for (int pr = tid; pr < NW * PT; pr += 320) {
        const int w = pr >> 2, p = pr & 3;
        const float* frow = &Fs[w * FS + p * NQ];
        float fr[NQ];
#pragma unroll
        for (int c = 0; c < 9; c++) *(float4*)&fr[4 * c] = *(const float4*)&frow[4 * c];
        float m = fr[0];
#pragma unroll
        for (int q = 1; q < NQ; q++) m = fmaxf(m, fr[q]);
        float s = 0.0f, a = 0.0f;
        for (int q = 0; q < NQ; q++) {
            float u = 0.0f;
#pragma unroll
            for (int rv = 0; rv < 9; rv++) {
                float4 w4 = *(float4*)&Wps[q * NQ + 4 * rv];
                u += w4.x * fr[4 * rv] + w4.y * fr[4 * rv + 1] +
                     w4.z * fr[4 * rv + 2] + w4.w * fr[4 * rv + 3];
            }
            const float e = __expf((fr[q] - m) * TAU_INV);
            s += e;
            a += e * u;
        }
        g_plv[(size_t)b * (NW * NP) + w * NP + pb * PT + p] = a / s;
    }
}

// ---------------------------------------------------------------------------
// K3: per b: s2p/p2w second-level reductions -> sim[b][p]
// ---------------------------------------------------------------------------
__global__ void __launch_bounds__(128) k3_stage2(const float* __restrict__ Ww2,
                                                 const float* __restrict__ Wp2) {
    extern __shared__ float sm[];
    float* wls = sm;            // 4608
    float* pls = sm + 4608;     // 10240
    float* W2s = sm + 14848;    // 6400
    float* P2s = sm + 21248;    // 1296
    const int b = blockIdx.x, tid = threadIdx.x;

    const float4* s1 = (const float4*)(g_wl + (size_t)b * (NP * NQ));
    for (int i = tid; i < 1152; i += 128) ((float4*)wls)[i] = s1[i];
    const float4* s2 = (const float4*)(g_plv + (size_t)b * (NW * NP));
    for (int i = tid; i < 2560; i += 128) ((float4*)pls)[i] = s2[i];
    for (int i = tid; i < 1600; i += 128) ((float4*)W2s)[i] = ((const float4*)Ww2)[i];
    for (int i = tid; i < 324;  i += 128) ((float4*)P2s)[i] = ((const float4*)Wp2)[i];
    __syncthreads();

    const int p = tid;
    float fr[NQ];
#pragma unroll
    for (int c = 0; c < 9; c++) *(float4*)&fr[4 * c] = *(float4*)&wls[p * NQ + 4 * c];
    float m = fr[0];
#pragma unroll
    for (int q = 1; q < NQ; q++) m = fmaxf(m, fr[q]);
    float s = 0.0f, a = 0.0f;
    for (int q = 0; q < NQ; q++) {
        float u = 0.0f;
#pragma unroll
        for (int rv = 0; rv < 9; rv++) {
            float4 w4 = *(float4*)&P2s[q * NQ + 4 * rv];
            u += w4.x * fr[4 * rv] + w4.y * fr[4 * rv + 1] +
                 w4.z * fr[4 * rv + 2] + w4.w * fr[4 * rv + 3];
        }
        const float e = __expf((fr[q] - m) * TAU_INV);
        s += e; a += e * u;
    }
    const float s2p = a / s;

    float fw[NW];
    for (int w = 0; w < NW; w++) fw[w] = pls[w * NP + p];
    m = fw[0];
#pragma unroll
    for (int w = 1; w < NW; w++) m = fmaxf(m, fw[w]);
    s = 0.0f; a = 0.0f;
    for (int w = 0; w < NW; w++) {
        float u = 0.0f;
#pragma unroll
        for (int v4 = 0; v4 < 20; v4++) {
            float4 w4 = *(float4*)&W2s[w * NW + 4 * v4];
            u += w4.x * fw[4 * v4] + w4.y * fw[4 * v4 + 1] +
                 w4.z * fw[4 * v4 + 2] + w4.w * fw[4 * v4 + 3];
        }
        const float e = __expf((fw[w] - m) * TAU_INV);
        s += e; a += e * u;
    }
    const float p2w = a / s;

    g_sim[b * NP + p] = 0.5f * (s2p + p2w);
}

// ---------------------------------------------------------------------------
// K4 v2: 256 threads — row-LSE and col-LSE computed concurrently.
// ---------------------------------------------------------------------------
__global__ void __launch_bounds__(256) k4_loss(float* __restrict__ out) {
    extern __shared__ float sm[];
    float* sims = sm;                   // 128*129 (padded)
    float* lse  = sm + 128 * 129;       // 256
    float* red  = sm + 128 * 129 + 256; // 128
    const int tid = threadIdx.x;
    for (int i = tid; i < BS * NP; i += 256) {
        const int r = i >> 7, c = i & 127;
        sims[r * 129 + c] = g_sim[i];
    }
    __syncthreads();
    const int i = tid & 127;
    if (tid < 128) {
        float m = -1e30f;
        for (int j = 0; j < 128; j++) m = fmaxf(m, sims[i * 129 + j]);
        float s = 0.0f;
        for (int j = 0; j < 128; j++) s += expf(sims[i * 129 + j] - m);
        lse[i] = m + logf(s);
    } else {
        float m = -1e30f;
        for (int j = 0; j < 128; j++) m = fmaxf(m, sims[j * 129 + i]);
        float s = 0.0f;
        for (int j = 0; j < 128; j++) s += expf(sims[j * 129 + i] - m);
        lse[128 + i] = m + logf(s);
    }
    __syncthreads();
    if (tid < 128)
        red[i] = sims[i * 129 + i] - 0.5f * (lse[i] + lse[128 + i]);
    __syncthreads();
    for (int st = 64; st > 0; st >>= 1) {
        if (tid < st) red[tid] += red[tid + st];
        __syncthreads();
    }
    if (tid == 0) out[0] = -red[0] / 128.0f;
}

// ---------------------------------------------------------------------------
extern "C" void kernel_launch(void* const* d_in, const int* in_sizes, int n_in,
                              void* d_out, int out_size) {
    const float* patch = (const float*)d_in[0];  // (128, 36, 768)
    const float* word  = (const float*)d_in[1];  // (128, 80, 768)
    const float* L     = (const float*)d_in[2];  // (768, 768)
    const float* Ww    = (const float*)d_in[3];  // (80, 80)
    const float* Wp    = (const float*)d_in[4];  // (36, 36)
    const float* Ww2   = (const float*)d_in[5];  // (80, 80)
    const float* Wp2   = (const float*)d_in[6];  // (36, 36)
    float* out = (float*)d_out;

    const int smem_k1 = 5376 * 4;
    const int smem_k2 = 22192 * 4;
    const int smem_k3 = 22544 * 4;
    const int smem_k4 = (128 * 129 + 256 + 128) * 4;
    cudaFuncSetAttribute(k1_plgemm, cudaFuncAttributeMaxDynamicSharedMemorySize, smem_k1);
    cudaFuncSetAttribute(k2_fine,   cudaFuncAttributeMaxDynamicSharedMemorySize, smem_k2);
    cudaFuncSetAttribute(k3_stage2, cudaFuncAttributeMaxDynamicSharedMemorySize, smem_k3);
    cudaFuncSetAttribute(k4_loss,   cudaFuncAttributeMaxDynamicSharedMemorySize, smem_k4);

    k1_plgemm<<<dim3(8, 36), 256, smem_k1>>>(patch, L);
    k2_fine<<<dim3(NP / PT, BS), 320, smem_k2>>>(word, Ww, Wp);
    k3_stage2<<<BS, 128, smem_k3>>>(Ww2, Wp2);
    k4_loss<<<1, 256, smem_k4>>>(out);
}

// round 15
// speedup vs baseline: 1.6295x; 1.0489x over previous
#include <cuda_runtime.h>
#include <cuda_fp16.h>
#include <math.h>
#include <stdint.h>

// Problem constants
#define BS   128
#define NW   80
#define NP   128
#define NQ   36
#define DIM  768
#define TAU_INV 100.0f

#define PT   4            // patches per K2 block
#define NT   144          // PT*NQ columns per tile
#define FS   148          // F row stride in smem
#define GSW  76           // G row stride in words (fp16 pairs), bank-perfect
#define WWS  44           // Ww fp16 row stride in words, bank-perfect

// Scratch (device globals: no allocation allowed)
__device__ float g_pl [NP*NQ*DIM];    // 4608 x 768  : patch @ L^T
__device__ float g_wl [BS*NP*NQ];     // word_level [b][p][q]
__device__ float g_plv[BS*NW*NP];     // patch_level [b][w][p]
__device__ float g_sim[BS*NP];        // sim [b][p]

// ---------------------------------------------------------------------------
// helpers
// ---------------------------------------------------------------------------
__device__ __forceinline__ uint32_t pack_f16(float lo_elem, float hi_elem) {
    uint32_t r;
    asm("cvt.rn.f16x2.f32 %0, %1, %2;" : "=r"(r) : "f"(hi_elem), "f"(lo_elem));
    return r;
}
__device__ __forceinline__ void pack4_f16(float4 v, uint32_t* hp) {
    hp[0] = pack_f16(v.x, v.y);
    hp[1] = pack_f16(v.z, v.w);
}
__device__ __forceinline__ void mma_f16(float4& d,
    uint32_t a0, uint32_t a1, uint32_t a2, uint32_t a3,
    uint32_t b0, uint32_t b1) {
    asm volatile(
        "mma.sync.aligned.m16n8k16.row.col.f32.f16.f16.f32 "
        "{%0,%1,%2,%3}, {%4,%5,%6,%7}, {%8,%9}, {%0,%1,%2,%3};\n"
        : "+f"(d.x), "+f"(d.y), "+f"(d.z), "+f"(d.w)
        : "r"(a0), "r"(a1), "r"(a2), "r"(a3), "r"(b0), "r"(b1));
}

// ---------------------------------------------------------------------------
// K1 v3: pl = patch2d @ L^T, pure fp16 mma (single product, f32 acc).
// ---------------------------------------------------------------------------
#define K1PRS 12
#define K1_STG 2688

__global__ void __launch_bounds__(256, 2) k1_plgemm(const float* __restrict__ patch,
                                                    const float* __restrict__ L) {
    extern __shared__ float smf[];
    uint32_t* smw = (uint32_t*)smf;
    const int tid = threadIdx.x;
    const int lane = tid & 31, wid = tid >> 5;
    const int g = lane >> 2, t4 = lane & 3;
    const int mw = wid >> 1, nw = wid & 1;
    const int m0 = blockIdx.y * 128;
    const int n0 = blockIdx.x * 96;
    const float* Ap = patch + (size_t)m0 * DIM;
    const float* Bp = L + (size_t)n0 * DIM;

    float4 pa[2], pb[2];
#pragma unroll
    for (int j = 0; j < 2; j++) {
        const int pos = tid + 256 * j;
        pa[j] = *(const float4*)&Ap[(pos >> 2) * DIM + 4 * (pos & 3)];
    }
#pragma unroll
    for (int j = 0; j < 2; j++) {
        const int pos = tid + 256 * j;
        if (pos < 384)
            pb[j] = *(const float4*)&Bp[(pos >> 2) * DIM + 4 * (pos & 3)];
    }

    float4 acc[2][6];
#pragma unroll
    for (int i = 0; i < 2; i++)
#pragma unroll
        for (int j = 0; j < 6; j++) acc[i][j] = make_float4(0.f, 0.f, 0.f, 0.f);

    for (int kc = 0; kc < 48; kc++) {
        __syncthreads();
        uint32_t* Ah = smw + (kc & 1) * K1_STG;
        uint32_t* Bh = Ah + 1536;
#pragma unroll
        for (int j = 0; j < 2; j++) {
            const int pos = tid + 256 * j, r = pos >> 2, c4 = pos & 3;
            uint32_t hp[2];
            pack4_f16(pa[j], hp);
            *(uint2*)&Ah[r * K1PRS + 2 * c4] = make_uint2(hp[0], hp[1]);
        }
#pragma unroll
        for (int j = 0; j < 2; j++) {
            const int pos = tid + 256 * j;
            if (pos < 384) {
                const int r = pos >> 2, c4 = pos & 3;
                uint32_t hp[2];
                pack4_f16(pb[j], hp);
                *(uint2*)&Bh[r * K1PRS + 2 * c4] = make_uint2(hp[0], hp[1]);
            }
        }
        __syncthreads();
        if (kc < 47) {
            const int kn = (kc + 1) * 16;
#pragma unroll
            for (int j = 0; j < 2; j++) {
                const int pos = tid + 256 * j;
                pa[j] = *(const float4*)&Ap[(pos >> 2) * DIM + kn + 4 * (pos & 3)];
            }
#pragma unroll
            for (int j = 0; j < 2; j++) {
                const int pos = tid + 256 * j;
                if (pos < 384)
                    pb[j] = *(const float4*)&Bp[(pos >> 2) * DIM + kn + 4 * (pos & 3)];
            }
        }
#pragma unroll
        for (int mt = 0; mt < 2; mt++) {
            const int arow = (mw * 32 + mt * 16 + g) * K1PRS + t4;
            const uint32_t a0 = Ah[arow];
            const uint32_t a1 = Ah[arow + 8 * K1PRS];
            const uint32_t a2 = Ah[arow + 4];
            const uint32_t a3 = Ah[arow + 8 * K1PRS + 4];
#pragma unroll
            for (int nt = 0; nt < 6; nt++) {
                const int brow = (nw * 48 + nt * 8 + g) * K1PRS + t4;
                mma_f16(acc[mt][nt], a0, a1, a2, a3, Bh[brow], Bh[brow + 4]);
            }
        }
    }

#pragma unroll
    for (int mt = 0; mt < 2; mt++) {
#pragma unroll
        for (int nt = 0; nt < 6; nt++) {
            const int row = m0 + mw * 32 + mt * 16 + g;
            const int col = n0 + nw * 48 + nt * 8 + 2 * t4;
            g_pl[(size_t)row * DIM + col]           = acc[mt][nt].x;
            g_pl[(size_t)row * DIM + col + 1]       = acc[mt][nt].y;
            g_pl[(size_t)(row + 8) * DIM + col]     = acc[mt][nt].z;
            g_pl[(size_t)(row + 8) * DIM + col + 1] = acc[mt][nt].w;
        }
    }
}

// ---------------------------------------------------------------------------
// K2 v9: fp16 mma mainloop + tensor-core G-GEMM epilogue, 2 CTAs/SM.
// smem layout (floats/words):
//   mainloop buffers: 2 x 4480 words @0  -> 0..8960
//   Fs@0 (11840), red@11840 (2368)       -> 0..14208   (aliases buffers)
//   Gs@14208 (6080 words, fp16 pairs, stride 76)
//   Wwh@20288 (3520 words, Ww fp16 pairs, stride 44)
//   Wps@23808 (1296), cmax@25104 (144), csum@25248 (144)
// total 25392 floats = 101568 B -> 2 CTAs/SM
// ---------------------------------------------------------------------------
#define SMW_BUF 4480
#define PRS 20          // pair-row stride in words

__global__ void __launch_bounds__(320, 2) k2_fine(const float* __restrict__ word,
                                                  const float* __restrict__ Ww,
                                                  const float* __restrict__ Wp) {
    extern __shared__ float sm[];
    uint32_t* smw = (uint32_t*)sm;
    float* Fs   = sm;                       // 11840
    float* red  = sm + 11840;               // 2368
    uint32_t* Gsw = (uint32_t*)(sm + 14208);   // 6080 words
    uint32_t* Wwh = (uint32_t*)(sm + 20288);   // 3520 words
    float* Wps  = sm + 23808;               // 1296
    float* cmax = sm + 25104;               // 144
    float* csum = sm + 25248;               // 144

    const int tid  = threadIdx.x;
    const int lane = tid & 31, wid = tid >> 5;
    const int g  = lane >> 2, t4 = lane & 3;
    const int ms = wid >> 1,  ns = wid & 1;        // wid 0..9
    const int b = blockIdx.y, pb = blockIdx.x;

    // stage Ww as fp16 pairs (stride 44 words) and Wp fp32
    for (int i = tid; i < 3200; i += 320) {
        const int r = i / 40, k2 = i % 40;
        Wwh[r * WWS + k2] = pack_f16(Ww[r * 80 + 2 * k2], Ww[r * 80 + 2 * k2 + 1]);
    }
    for (int i = tid; i < 324; i += 320) ((float4*)Wps)[i] = ((const float4*)Wp)[i];

    const float* Aw = word + (size_t)b * NW * DIM;
    const float* Bp = g_pl + (size_t)pb * NT * DIM;   // 144 contiguous rows

    float4 pa[2], pb4[4];
#pragma unroll
    for (int j = 0; j < 2; j++) {
        const int pos = tid + 320 * j;                 // < 640
        pa[j] = *(const float4*)&Aw[(pos >> 3) * DIM + 4 * (pos & 7)];
    }
#pragma unroll
    for (int j = 0; j < 4; j++) {
        const int pos = tid + 320 * j;
        if (pos < 1152)
            pb4[j] = *(const float4*)&Bp[(pos >> 3) * DIM + 4 * (pos & 7)];
    }

    float4 acc[9];
#pragma unroll
    for (int j = 0; j < 9; j++) acc[j] = make_float4(0.f, 0.f, 0.f, 0.f);

    for (int kc = 0; kc < 24; kc++) {
        __syncthreads();
        uint32_t* Ah = smw + (kc & 1) * SMW_BUF;
        uint32_t* Bh = Ah + 1600;
#pragma unroll
        for (int j = 0; j < 2; j++) {
            const int pos = tid + 320 * j, r = pos >> 3, c4 = pos & 7;
            uint32_t hp[2];
            pack4_f16(pa[j], hp);
            *(uint2*)&Ah[r * PRS + 2 * c4] = make_uint2(hp[0], hp[1]);
        }
#pragma unroll
        for (int j = 0; j < 4; j++) {
            const int pos = tid + 320 * j;
            if (pos < 1152) {
                const int r = pos >> 3, c4 = pos & 7;
                uint32_t hp[2];
                pack4_f16(pb4[j], hp);
                *(uint2*)&Bh[r * PRS + 2 * c4] = make_uint2(hp[0], hp[1]);
            }
        }
        __syncthreads();
        if (kc < 23) {
            const int kn = (kc + 1) * 32;
#pragma unroll
            for (int j = 0; j < 2; j++) {
                const int pos = tid + 320 * j;
                pa[j] = *(const float4*)&Aw[(pos >> 3) * DIM + kn + 4 * (pos & 7)];
            }
#pragma unroll
            for (int j = 0; j < 4; j++) {
                const int pos = tid + 320 * j;
                if (pos < 1152)
                    pb4[j] = *(const float4*)&Bp[(pos >> 3) * DIM + kn + 4 * (pos & 7)];
            }
        }
#pragma unroll
        for (int ks = 0; ks < 2; ks++) {
            const int arow = (16 * ms + g) * PRS + ks * 8 + t4;
            const uint32_t a0 = Ah[arow];
            const uint32_t a1 = Ah[arow + 8 * PRS];
            const uint32_t a2 = Ah[arow + 4];
            const uint32_t a3 = Ah[arow + 8 * PRS + 4];
#pragma unroll
            for (int nt = 0; nt < 9; nt++) {
                const int brow = (72 * ns + 8 * nt + g) * PRS + ks * 8 + t4;
                mma_f16(acc[nt], a0, a1, a2, a3, Bh[brow], Bh[brow + 4]);
            }
        }
    }
    __syncthreads();

    // F tile -> smem (C fragment layout: rows g/g+8, cols 2t4, 2t4+1)
#pragma unroll
    for (int nt = 0; nt < 9; nt++) {
        const int row = 16 * ms + g, col = 72 * ns + 8 * nt + 2 * t4;
        Fs[row * FS + col]           = acc[nt].x;
        Fs[row * FS + col + 1]       = acc[nt].y;
        Fs[(row + 8) * FS + col]     = acc[nt].z;
        Fs[(row + 8) * FS + col + 1] = acc[nt].w;
    }
    __syncthreads();

    // phase A: column softmax stats (tid<144)  +  G = Ww @ F via mma (all warps)
    if (tid < NT) {
        float m = -1e30f;
        for (int w = 0; w < NW; w++) m = fmaxf(m, Fs[w * FS + tid]);
        float s = 0.0f;
        for (int w = 0; w < NW; w++) s += __expf((Fs[w * FS + tid] - m) * TAU_INV);
        cmax[tid] = m;
        csum[tid] = s;
    }
    // G-mma: warp (ms,ns) covers rows [16ms,16ms+16), cols [72ns,72ns+72)
#pragma unroll
    for (int j = 0; j < 9; j++) acc[j] = make_float4(0.f, 0.f, 0.f, 0.f);
#pragma unroll
    for (int ks = 0; ks < 5; ks++) {
        const int ar = (16 * ms + g) * WWS + ks * 8 + t4;
        const uint32_t a0 = Wwh[ar];
        const uint32_t a1 = Wwh[ar + 8 * WWS];
        const uint32_t a2 = Wwh[ar + 4];
        const uint32_t a3 = Wwh[ar + 8 * WWS + 4];
        const int v0 = 16 * ks + 2 * t4;
#pragma unroll
        for (int nt = 0; nt < 9; nt++) {
            const int c = 72 * ns + 8 * nt + g;
            const uint32_t b0 = pack_f16(Fs[v0 * FS + c],       Fs[(v0 + 1) * FS + c]);
            const uint32_t b1 = pack_f16(Fs[(v0 + 8) * FS + c], Fs[(v0 + 9) * FS + c]);
            mma_f16(acc[nt], a0, a1, a2, a3, b0, b1);
        }
    }
    // store G fragments as fp16 pairs (cols 2t4,2t4+1 -> one word)
#pragma unroll
    for (int nt = 0; nt < 9; nt++) {
        const int row = 16 * ms + g, cw = 36 * ns + 4 * nt + t4;
        Gsw[row * GSW + cw]       = pack_f16(acc[nt].x, acc[nt].y);
        Gsw[(row + 8) * GSW + cw] = pack_f16(acc[nt].z, acc[nt].w);
    }
    __syncthreads();

    // phase B: per-thread partial  sum_i e(F[ty+16i][c]) * G[ty+16i][c] -> red
    if (tid < 256) {
        const int tx = tid & 15, ty = tid >> 4;
        const int par = tx & 1;
#pragma unroll
        for (int j = 0; j < 9; j++) {
            const int c = tx + 16 * j;
            const float m = cmax[c];
            float part = 0.0f;
#pragma unroll
            for (int i = 0; i < 5; i++) {
                const int row = ty + 16 * i;
                const uint32_t gw = Gsw[row * GSW + (c >> 1)];
                const __half2 h2 = *reinterpret_cast<const __half2*>(&gw);
                const float gval = par ? __high2float(h2) : __low2float(h2);
                part += __expf((Fs[row * FS + c] - m) * TAU_INV) * gval;
            }
            red[ty * FS + c] = part;
        }
    }
    __syncthreads();

    // phase C: word_level = (sum_ty red[ty][c]) / csum[c]
    if (tid < NT) {
        float a = 0.0f;
#pragma unroll
        for (int t = 0; t < 16; t++) a += red[t * FS + tid];
        g_wl[(size_t)b * (NP * NQ) + pb * NT + tid] = a / csum[tid];
    }

    // patch_level[b, w, pb*4 + p]  (NW*PT = 320: one row per thread)
    for (int pr = tid; pr < NW * PT; pr += 320) {
        const int w = pr >> 2, p = pr & 3;
        const float* frow = &Fs[w * FS + p * NQ];
        float fr[NQ];
#pragma unroll
        for (int c = 0; c < 9; c++) *(float4*)&fr[4 * c] = *(const float4*)&frow[4 * c];
        float m = fr[0];
#pragma unroll
        for (int q = 1; q < NQ; q++) m = fmaxf(m, fr[q]);
        float s = 0.0f, a = 0.0f;
        for (int q = 0; q < NQ; q++) {
            float u = 0.0f;
#pragma unroll
            for (int rv = 0; rv < 9; rv++) {
                float4 w4 = *(float4*)&Wps[q * NQ + 4 * rv];
                u += w4.x * fr[4 * rv] + w4.y * fr[4 * rv + 1] +
                     w4.z * fr[4 * rv + 2] + w4.w * fr[4 * rv + 3];
            }
            const float e = __expf((fr[q] - m) * TAU_INV);
            s += e;
            a += e * u;
        }
        g_plv[(size_t)b * (NW * NP) + w * NP + pb * PT + p] = a / s;
    }
}

// ---------------------------------------------------------------------------
// K3: per b: s2p/p2w second-level reductions -> sim[b][p]
// ---------------------------------------------------------------------------
__global__ void __launch_bounds__(128) k3_stage2(const float* __restrict__ Ww2,
                                                 const float* __restrict__ Wp2) {
    extern __shared__ float sm[];
    float* wls = sm;            // 4608
    float* pls = sm + 4608;     // 10240
    float* W2s = sm + 14848;    // 6400
    float* P2s = sm + 21248;    // 1296
    const int b = blockIdx.x, tid = threadIdx.x;

    const float4* s1 = (const float4*)(g_wl + (size_t)b * (NP * NQ));
    for (int i = tid; i < 1152; i += 128) ((float4*)wls)[i] = s1[i];
    const float4* s2 = (const float4*)(g_plv + (size_t)b * (NW * NP));
    for (int i = tid; i < 2560; i += 128) ((float4*)pls)[i] = s2[i];
    for (int i = tid; i < 1600; i += 128) ((float4*)W2s)[i] = ((const float4*)Ww2)[i];
    for (int i = tid; i < 324;  i += 128) ((float4*)P2s)[i] = ((const float4*)Wp2)[i];
    __syncthreads();

    const int p = tid;
    float fr[NQ];
#pragma unroll
    for (int c = 0; c < 9; c++) *(float4*)&fr[4 * c] = *(float4*)&wls[p * NQ + 4 * c];
    float m = fr[0];
#pragma unroll
    for (int q = 1; q < NQ; q++) m = fmaxf(m, fr[q]);
    float s = 0.0f, a = 0.0f;
    for (int q = 0; q < NQ; q++) {
        float u = 0.0f;
#pragma unroll
        for (int rv = 0; rv < 9; rv++) {
            float4 w4 = *(float4*)&P2s[q * NQ + 4 * rv];
            u += w4.x * fr[4 * rv] + w4.y * fr[4 * rv + 1] +
                 w4.z * fr[4 * rv + 2] + w4.w * fr[4 * rv + 3];
        }
        const float e = __expf((fr[q] - m) * TAU_INV);
        s += e; a += e * u;
    }
    const float s2p = a / s;

    float fw[NW];
    for (int w = 0; w < NW; w++) fw[w] = pls[w * NP + p];
    m = fw[0];
#pragma unroll
    for (int w = 1; w < NW; w++) m = fmaxf(m, fw[w]);
    s = 0.0f; a = 0.0f;
    for (int w = 0; w < NW; w++) {
        float u = 0.0f;
#pragma unroll
        for (int v4 = 0; v4 < 20; v4++) {
            float4 w4 = *(float4*)&W2s[w * NW + 4 * v4];
            u += w4.x * fw[4 * v4] + w4.y * fw[4 * v4 + 1] +
                 w4.z * fw[4 * v4 + 2] + w4.w * fw[4 * v4 + 3];
        }
        const float e = __expf((fw[w] - m) * TAU_INV);
        s += e; a += e * u;
    }
    const float p2w = a / s;

    g_sim[b * NP + p] = 0.5f * (s2p + p2w);
}

// ---------------------------------------------------------------------------
// K4 v2: 256 threads — row-LSE and col-LSE computed concurrently.
// ---------------------------------------------------------------------------
__global__ void __launch_bounds__(256) k4_loss(float* __restrict__ out) {
    extern __shared__ float sm[];
    float* sims = sm;                   // 128*129 (padded)
    float* lse  = sm + 128 * 129;       // 256
    float* red  = sm + 128 * 129 + 256; // 128
    const int tid = threadIdx.x;
    for (int i = tid; i < BS * NP; i += 256) {
        const int r = i >> 7, c = i & 127;
        sims[r * 129 + c] = g_sim[i];
    }
    __syncthreads();
    const int i = tid & 127;
    if (tid < 128) {
        float m = -1e30f;
        for (int j = 0; j < 128; j++) m = fmaxf(m, sims[i * 129 + j]);
        float s = 0.0f;
        for (int j = 0; j < 128; j++) s += expf(sims[i * 129 + j] - m);
        lse[i] = m + logf(s);
    } else {
        float m = -1e30f;
        for (int j = 0; j < 128; j++) m = fmaxf(m, sims[j * 129 + i]);
        float s = 0.0f;
        for (int j = 0; j < 128; j++) s += expf(sims[j * 129 + i] - m);
        lse[128 + i] = m + logf(s);
    }
    __syncthreads();
    if (tid < 128)
        red[i] = sims[i * 129 + i] - 0.5f * (lse[i] + lse[128 + i]);
    __syncthreads();
    for (int st = 64; st > 0; st >>= 1) {
        if (tid < st) red[tid] += red[tid + st];
        __syncthreads();
    }
    if (tid == 0) out[0] = -red[0] / 128.0f;
}

// ---------------------------------------------------------------------------
extern "C" void kernel_launch(void* const* d_in, const int* in_sizes, int n_in,
                              void* d_out, int out_size) {
    const float* patch = (const float*)d_in[0];  // (128, 36, 768)
    const float* word  = (const float*)d_in[1];  // (128, 80, 768)
    const float* L     = (const float*)d_in[2];  // (768, 768)
    const float* Ww    = (const float*)d_in[3];  // (80, 80)
    const float* Wp    = (const float*)d_in[4];  // (36, 36)
    const float* Ww2   = (const float*)d_in[5];  // (80, 80)
    const float* Wp2   = (const float*)d_in[6];  // (36, 36)
    float* out = (float*)d_out;

    const int smem_k1 = 5376 * 4;
    const int smem_k2 = 25392 * 4;
    const int smem_k3 = 22544 * 4;
    const int smem_k4 = (128 * 129 + 256 + 128) * 4;
    cudaFuncSetAttribute(k1_plgemm, cudaFuncAttributeMaxDynamicSharedMemorySize, smem_k1);
    cudaFuncSetAttribute(k2_fine,   cudaFuncAttributeMaxDynamicSharedMemorySize, smem_k2);
    cudaFuncSetAttribute(k3_stage2, cudaFuncAttributeMaxDynamicSharedMemorySize, smem_k3);
    cudaFuncSetAttribute(k4_loss,   cudaFuncAttributeMaxDynamicSharedMemorySize, smem_k4);

    k1_plgemm<<<dim3(8, 36), 256, smem_k1>>>(patch, L);
    k2_fine<<<dim3(NP / PT, BS), 320, smem_k2>>>(word, Ww, Wp);
    k3_stage2<<<BS, 128, smem_k3>>>(Ww2, Wp2);
    k4_loss<<<1, 256, smem_k4>>>(out);
}

// round 16
// speedup vs baseline: 1.6375x; 1.0049x over previous
#include <cuda_runtime.h>
#include <cuda_fp16.h>
#include <math.h>
#include <stdint.h>

// Problem constants
#define BS   128
#define NW   80
#define NP   128
#define NQ   36
#define DIM  768
#define TAU_INV 100.0f

#define PT   4            // patches per K2 block
#define NT   144          // PT*NQ columns per tile
#define FS   148          // F row stride in smem
#define GSW  76           // G row stride in words (fp16 pairs), bank-perfect
#define WWS  44           // Ww fp16 row stride in words, bank-perfect

// Scratch (device globals: no allocation allowed)
__device__ float g_pl [NP*NQ*DIM];    // 4608 x 768  : patch @ L^T
__device__ float g_wl [BS*NP*NQ];     // word_level [b][p][q]
__device__ float g_plv[BS*NW*NP];     // patch_level [b][w][p]
__device__ float g_sim[BS*NP];        // sim [b][p]

// ---------------------------------------------------------------------------
// helpers
// ---------------------------------------------------------------------------
__device__ __forceinline__ uint32_t pack_f16(float lo_elem, float hi_elem) {
    uint32_t r;
    asm("cvt.rn.f16x2.f32 %0, %1, %2;" : "=r"(r) : "f"(hi_elem), "f"(lo_elem));
    return r;
}
__device__ __forceinline__ void pack4_f16(float4 v, uint32_t* hp) {
    hp[0] = pack_f16(v.x, v.y);
    hp[1] = pack_f16(v.z, v.w);
}
__device__ __forceinline__ void mma_f16(float4& d,
    uint32_t a0, uint32_t a1, uint32_t a2, uint32_t a3,
    uint32_t b0, uint32_t b1) {
    asm volatile(
        "mma.sync.aligned.m16n8k16.row.col.f32.f16.f16.f32 "
        "{%0,%1,%2,%3}, {%4,%5,%6,%7}, {%8,%9}, {%0,%1,%2,%3};\n"
        : "+f"(d.x), "+f"(d.y), "+f"(d.z), "+f"(d.w)
        : "r"(a0), "r"(a1), "r"(a2), "r"(a3), "r"(b0), "r"(b1));
}

// ---------------------------------------------------------------------------
// K1 v3: pl = patch2d @ L^T, pure fp16 mma (single product, f32 acc).
// ---------------------------------------------------------------------------
#define K1PRS 12
#define K1_STG 2688

__global__ void __launch_bounds__(256, 2) k1_plgemm(const float* __restrict__ patch,
                                                    const float* __restrict__ L) {
    extern __shared__ float smf[];
    uint32_t* smw = (uint32_t*)smf;
    const int tid = threadIdx.x;
    const int lane = tid & 31, wid = tid >> 5;
    const int g = lane >> 2, t4 = lane & 3;
    const int mw = wid >> 1, nw = wid & 1;
    const int m0 = blockIdx.y * 128;
    const int n0 = blockIdx.x * 96;
    const float* Ap = patch + (size_t)m0 * DIM;
    const float* Bp = L + (size_t)n0 * DIM;

    float4 pa[2], pb[2];
#pragma unroll
    for (int j = 0; j < 2; j++) {
        const int pos = tid + 256 * j;
        pa[j] = *(const float4*)&Ap[(pos >> 2) * DIM + 4 * (pos & 3)];
    }
#pragma unroll
    for (int j = 0; j < 2; j++) {
        const int pos = tid + 256 * j;
        if (pos < 384)
            pb[j] = *(const float4*)&Bp[(pos >> 2) * DIM + 4 * (pos & 3)];
    }

    float4 acc[2][6];
#pragma unroll
    for (int i = 0; i < 2; i++)
#pragma unroll
        for (int j = 0; j < 6; j++) acc[i][j] = make_float4(0.f, 0.f, 0.f, 0.f);

    for (int kc = 0; kc < 48; kc++) {
        __syncthreads();
        uint32_t* Ah = smw + (kc & 1) * K1_STG;
        uint32_t* Bh = Ah + 1536;
#pragma unroll
        for (int j = 0; j < 2; j++) {
            const int pos = tid + 256 * j, r = pos >> 2, c4 = pos & 3;
            uint32_t hp[2];
            pack4_f16(pa[j], hp);
            *(uint2*)&Ah[r * K1PRS + 2 * c4] = make_uint2(hp[0], hp[1]);
        }
#pragma unroll
        for (int j = 0; j < 2; j++) {
            const int pos = tid + 256 * j;
            if (pos < 384) {
                const int r = pos >> 2, c4 = pos & 3;
                uint32_t hp[2];
                pack4_f16(pb[j], hp);
                *(uint2*)&Bh[r * K1PRS + 2 * c4] = make_uint2(hp[0], hp[1]);
            }
        }
        __syncthreads();
        if (kc < 47) {
            const int kn = (kc + 1) * 16;
#pragma unroll
            for (int j = 0; j < 2; j++) {
                const int pos = tid + 256 * j;
                pa[j] = *(const float4*)&Ap[(pos >> 2) * DIM + kn + 4 * (pos & 3)];
            }
#pragma unroll
            for (int j = 0; j < 2; j++) {
                const int pos = tid + 256 * j;
                if (pos < 384)
                    pb[j] = *(const float4*)&Bp[(pos >> 2) * DIM + kn + 4 * (pos & 3)];
            }
        }
#pragma unroll
        for (int mt = 0; mt < 2; mt++) {
            const int arow = (mw * 32 + mt * 16 + g) * K1PRS + t4;
            const uint32_t a0 = Ah[arow];
            const uint32_t a1 = Ah[arow + 8 * K1PRS];
            const uint32_t a2 = Ah[arow + 4];
            const uint32_t a3 = Ah[arow + 8 * K1PRS + 4];
#pragma unroll
            for (int nt = 0; nt < 6; nt++) {
                const int brow = (nw * 48 + nt * 8 + g) * K1PRS + t4;
                mma_f16(acc[mt][nt], a0, a1, a2, a3, Bh[brow], Bh[brow + 4]);
            }
        }
    }

#pragma unroll
    for (int mt = 0; mt < 2; mt++) {
#pragma unroll
        for (int nt = 0; nt < 6; nt++) {
            const int row = m0 + mw * 32 + mt * 16 + g;
            const int col = n0 + nw * 48 + nt * 8 + 2 * t4;
            g_pl[(size_t)row * DIM + col]           = acc[mt][nt].x;
            g_pl[(size_t)row * DIM + col + 1]       = acc[mt][nt].y;
            g_pl[(size_t)(row + 8) * DIM + col]     = acc[mt][nt].z;
            g_pl[(size_t)(row + 8) * DIM + col + 1] = acc[mt][nt].w;
        }
    }
}

// ---------------------------------------------------------------------------
// K2 v10: fp16 mma mainloop + mma G-GEMM + single-exp epilogue, 2 CTAs/SM.
// smem layout (floats/words):
//   mainloop buffers: 2 x 4480 words @0 -> 0..8960
//   Fs@0 (11840; becomes E in place), red@11840 (2368)
//   Gsw@14208 (6080 words), Wwh@20288 (3520 words; becomes red2 after G-mma)
//   Wps@23808 (1296), cmax@25104 (144), [25248..25392 pad]
// total 25392 floats = 101568 B -> 2 CTAs/SM
// ---------------------------------------------------------------------------
#define SMW_BUF 4480
#define PRS 20          // pair-row stride in words

__global__ void __launch_bounds__(320, 2) k2_fine(const float* __restrict__ word,
                                                  const float* __restrict__ Ww,
                                                  const float* __restrict__ Wp) {
    extern __shared__ float sm[];
    uint32_t* smw = (uint32_t*)sm;
    float* Fs   = sm;                       // 11840 (F, then E in place)
    float* red  = sm + 11840;               // 2368
    uint32_t* Gsw = (uint32_t*)(sm + 14208);   // 6080 words
    uint32_t* Wwh = (uint32_t*)(sm + 20288);   // 3520 words
    float* red2 = sm + 20288;               // aliases Wwh after G-mma (2368 used)
    float* Wps  = sm + 23808;               // 1296
    float* cmax = sm + 25104;               // 144

    const int tid  = threadIdx.x;
    const int lane = tid & 31, wid = tid >> 5;
    const int g  = lane >> 2, t4 = lane & 3;
    const int ms = wid >> 1,  ns = wid & 1;        // wid 0..9
    const int b = blockIdx.y, pb = blockIdx.x;

    // stage Ww as fp16 pairs (stride 44 words) and Wp fp32
    for (int i = tid; i < 3200; i += 320) {
        const int r = i / 40, k2 = i % 40;
        Wwh[r * WWS + k2] = pack_f16(Ww[r * 80 + 2 * k2], Ww[r * 80 + 2 * k2 + 1]);
    }
    for (int i = tid; i < 324; i += 320) ((float4*)Wps)[i] = ((const float4*)Wp)[i];

    const float* Aw = word + (size_t)b * NW * DIM;
    const float* Bp = g_pl + (size_t)pb * NT * DIM;   // 144 contiguous rows

    float4 pa[2], pb4[4];
#pragma unroll
    for (int j = 0; j < 2; j++) {
        const int pos = tid + 320 * j;                 // < 640
        pa[j] = *(const float4*)&Aw[(pos >> 3) * DIM + 4 * (pos & 7)];
    }
#pragma unroll
    for (int j = 0; j < 4; j++) {
        const int pos = tid + 320 * j;
        if (pos < 1152)
            pb4[j] = *(const float4*)&Bp[(pos >> 3) * DIM + 4 * (pos & 7)];
    }

    float4 acc[9];
#pragma unroll
    for (int j = 0; j < 9; j++) acc[j] = make_float4(0.f, 0.f, 0.f, 0.f);

    for (int kc = 0; kc < 24; kc++) {
        __syncthreads();
        uint32_t* Ah = smw + (kc & 1) * SMW_BUF;
        uint32_t* Bh = Ah + 1600;
#pragma unroll
        for (int j = 0; j < 2; j++) {
            const int pos = tid + 320 * j, r = pos >> 3, c4 = pos & 7;
            uint32_t hp[2];
            pack4_f16(pa[j], hp);
            *(uint2*)&Ah[r * PRS + 2 * c4] = make_uint2(hp[0], hp[1]);
        }
#pragma unroll
        for (int j = 0; j < 4; j++) {
            const int pos = tid + 320 * j;
            if (pos < 1152) {
                const int r = pos >> 3, c4 = pos & 7;
                uint32_t hp[2];
                pack4_f16(pb4[j], hp);
                *(uint2*)&Bh[r * PRS + 2 * c4] = make_uint2(hp[0], hp[1]);
            }
        }
        __syncthreads();
        if (kc < 23) {
            const int kn = (kc + 1) * 32;
#pragma unroll
            for (int j = 0; j < 2; j++) {
                const int pos = tid + 320 * j;
                pa[j] = *(const float4*)&Aw[(pos >> 3) * DIM + kn + 4 * (pos & 7)];
            }
#pragma unroll
            for (int j = 0; j < 4; j++) {
                const int pos = tid + 320 * j;
                if (pos < 1152)
                    pb4[j] = *(const float4*)&Bp[(pos >> 3) * DIM + kn + 4 * (pos & 7)];
            }
        }
#pragma unroll
        for (int ks = 0; ks < 2; ks++) {
            const int arow = (16 * ms + g) * PRS + ks * 8 + t4;
            const uint32_t a0 = Ah[arow];
            const uint32_t a1 = Ah[arow + 8 * PRS];
            const uint32_t a2 = Ah[arow + 4];
            const uint32_t a3 = Ah[arow + 8 * PRS + 4];
#pragma unroll
            for (int nt = 0; nt < 9; nt++) {
                const int brow = (72 * ns + 8 * nt + g) * PRS + ks * 8 + t4;
                mma_f16(acc[nt], a0, a1, a2, a3, Bh[brow], Bh[brow + 4]);
            }
        }
    }
    __syncthreads();

    // F tile -> smem (C fragment layout: rows g/g+8, cols 2t4, 2t4+1)
#pragma unroll
    for (int nt = 0; nt < 9; nt++) {
        const int row = 16 * ms + g, col = 72 * ns + 8 * nt + 2 * t4;
        Fs[row * FS + col]           = acc[nt].x;
        Fs[row * FS + col + 1]       = acc[nt].y;
        Fs[(row + 8) * FS + col]     = acc[nt].z;
        Fs[(row + 8) * FS + col + 1] = acc[nt].w;
    }
    __syncthreads();

    // phase A1: 16-way partial column max (256 threads, 5 rows each)
    if (tid < 256) {
        const int tx = tid & 15, ty = tid >> 4;
#pragma unroll
        for (int j = 0; j < 9; j++) {
            const int c = tx + 16 * j;
            float m = -1e30f;
#pragma unroll
            for (int i = 0; i < 5; i++) m = fmaxf(m, Fs[(ty + 16 * i) * FS + c]);
            red[ty * FS + c] = m;
        }
    }
    __syncthreads();

    // phase A2: cmax reduce (tid<144) + G-mma (all warps) + patch_level (all threads)
    if (tid < NT) {
        float m = red[tid];
#pragma unroll
        for (int t = 1; t < 16; t++) m = fmaxf(m, red[t * FS + tid]);
        cmax[tid] = m;
    }
    // G-mma: warp (ms,ns) covers rows [16ms,16ms+16), cols [72ns,72ns+72)
#pragma unroll
    for (int j = 0; j < 9; j++) acc[j] = make_float4(0.f, 0.f, 0.f, 0.f);
#pragma unroll
    for (int ks = 0; ks < 5; ks++) {
        const int ar = (16 * ms + g) * WWS + ks * 8 + t4;
        const uint32_t a0 = Wwh[ar];
        const uint32_t a1 = Wwh[ar + 8 * WWS];
        const uint32_t a2 = Wwh[ar + 4];
        const uint32_t a3 = Wwh[ar + 8 * WWS + 4];
        const int v0 = 16 * ks + 2 * t4;
#pragma unroll
        for (int nt = 0; nt < 9; nt++) {
            const int c = 72 * ns + 8 * nt + g;
            const uint32_t b0 = pack_f16(Fs[v0 * FS + c],       Fs[(v0 + 1) * FS + c]);
            const uint32_t b1 = pack_f16(Fs[(v0 + 8) * FS + c], Fs[(v0 + 9) * FS + c]);
            mma_f16(acc[nt], a0, a1, a2, a3, b0, b1);
        }
    }
#pragma unroll
    for (int nt = 0; nt < 9; nt++) {
        const int row = 16 * ms + g, cw = 36 * ns + 4 * nt + t4;
        Gsw[row * GSW + cw]       = pack_f16(acc[nt].x, acc[nt].y);
        Gsw[(row + 8) * GSW + cw] = pack_f16(acc[nt].z, acc[nt].w);
    }
    // patch_level[b, w, pb*4 + p]  (reads original F; one row per thread)
    for (int pr = tid; pr < NW * PT; pr += 320) {
        const int w = pr >> 2, p = pr & 3;
        const float* frow = &Fs[w * FS + p * NQ];
        float fr[NQ];
#pragma unroll
        for (int c = 0; c < 9; c++) *(float4*)&fr[4 * c] = *(const float4*)&frow[4 * c];
        float m = fr[0];
#pragma unroll
        for (int q = 1; q < NQ; q++) m = fmaxf(m, fr[q]);
        float s = 0.0f, a = 0.0f;
        for (int q = 0; q < NQ; q++) {
            float u = 0.0f;
#pragma unroll
            for (int rv = 0; rv < 9; rv++) {
                float4 w4 = *(float4*)&Wps[q * NQ + 4 * rv];
                u += w4.x * fr[4 * rv] + w4.y * fr[4 * rv + 1] +
                     w4.z * fr[4 * rv + 2] + w4.w * fr[4 * rv + 3];
            }
            const float e = __expf((fr[q] - m) * TAU_INV);
            s += e;
            a += e * u;
        }
        g_plv[(size_t)b * (NW * NP) + w * NP + pb * PT + p] = a / s;
    }
    __syncthreads();   // all F readers done; cmax ready; Gsw published

    // phase E: Fs := exp((Fs - cmax[c]) * tau) in place  (the ONLY column exps)
    for (int idx = tid; idx < NW * NT; idx += 320) {
        const int w = idx / NT, c = idx - w * NT;
        Fs[w * FS + c] = __expf((Fs[w * FS + c] - cmax[c]) * TAU_INV);
    }
    __syncthreads();

    // phase C1: 16-way partials of csum and sum(E*G)  (Wwh now dead -> red2)
    if (tid < 256) {
        const int tx = tid & 15, ty = tid >> 4;
        const int par = tx & 1;
#pragma unroll
        for (int j = 0; j < 9; j++) {
            const int c = tx + 16 * j;
            float se = 0.0f, seg = 0.0f;
#pragma unroll
            for (int i = 0; i < 5; i++) {
                const int row = ty + 16 * i;
                const float e = Fs[row * FS + c];
                const uint32_t gw = Gsw[row * GSW + (c >> 1)];
                const __half2 h2 = *reinterpret_cast<const __half2*>(&gw);
                const float gval = par ? __high2float(h2) : __low2float(h2);
                se += e;
                seg += e * gval;
            }
            red[ty * FS + c]  = se;
            red2[ty * FS + c] = seg;
        }
    }
    __syncthreads();

    // phase C2: word_level = sum(E*G) / sum(E)
    if (tid < NT) {
        float s = 0.0f, a = 0.0f;
#pragma unroll
        for (int t = 0; t < 16; t++) {
            s += red[t * FS + tid];
            a += red2[t * FS + tid];
        }
        g_wl[(size_t)b * (NP * NQ) + pb * NT + tid] = a / s;
    }
}

// ---------------------------------------------------------------------------
// K3: per b: s2p/p2w second-level reductions -> sim[b][p]
// ---------------------------------------------------------------------------
__global__ void __launch_bounds__(128) k3_stage2(const float* __restrict__ Ww2,
                                                 const float* __restrict__ Wp2) {
    extern __shared__ float sm[];
    float* wls = sm;            // 4608
    float* pls = sm + 4608;     // 10240
    float* W2s = sm + 14848;    // 6400
    float* P2s = sm + 21248;    // 1296
    const int b = blockIdx.x, tid = threadIdx.x;

    const float4* s1 = (const float4*)(g_wl + (size_t)b * (NP * NQ));
    for (int i = tid; i < 1152; i += 128) ((float4*)wls)[i] = s1[i];
    const float4* s2 = (const float4*)(g_plv + (size_t)b * (NW * NP));
    for (int i = tid; i < 2560; i += 128) ((float4*)pls)[i] = s2[i];
    for (int i = tid; i < 1600; i += 128) ((float4*)W2s)[i] = ((const float4*)Ww2)[i];
    for (int i = tid; i < 324;  i += 128) ((float4*)P2s)[i] = ((const float4*)Wp2)[i];
    __syncthreads();

    const int p = tid;
    float fr[NQ];
#pragma unroll
    for (int c = 0; c < 9; c++) *(float4*)&fr[4 * c] = *(float4*)&wls[p * NQ + 4 * c];
    float m = fr[0];
#pragma unroll
    for (int q = 1; q < NQ; q++) m = fmaxf(m, fr[q]);
    float s = 0.0f, a = 0.0f;
    for (int q = 0; q < NQ; q++) {
        float u = 0.0f;
#pragma unroll
        for (int rv = 0; rv < 9; rv++) {
            float4 w4 = *(float4*)&P2s[q * NQ + 4 * rv];
            u += w4.x * fr[4 * rv] + w4.y * fr[4 * rv + 1] +
                 w4.z * fr[4 * rv + 2] + w4.w * fr[4 * rv + 3];
        }
        const float e = __expf((fr[q] - m) * TAU_INV);
        s += e; a += e * u;
    }
    const float s2p = a / s;

    float fw[NW];
    for (int w = 0; w < NW; w++) fw[w] = pls[w * NP + p];
    m = fw[0];
#pragma unroll
    for (int w = 1; w < NW; w++) m = fmaxf(m, fw[w]);
    s = 0.0f; a = 0.0f;
    for (int w = 0; w < NW; w++) {
        float u = 0.0f;
#pragma unroll
        for (int v4 = 0; v4 < 20; v4++) {
            float4 w4 = *(float4*)&W2s[w * NW + 4 * v4];
            u += w4.x * fw[4 * v4] + w4.y * fw[4 * v4 + 1] +
                 w4.z * fw[4 * v4 + 2] + w4.w * fw[4 * v4 + 3];
        }
        const float e = __expf((fw[w] - m) * TAU_INV);
        s += e; a += e * u;
    }
    const float p2w = a / s;

    g_sim[b * NP + p] = 0.5f * (s2p + p2w);
}

// ---------------------------------------------------------------------------
// K4 v2: 256 threads — row-LSE and col-LSE computed concurrently.
// ---------------------------------------------------------------------------
__global__ void __launch_bounds__(256) k4_loss(float* __restrict__ out) {
    extern __shared__ float sm[];
    float* sims = sm;                   // 128*129 (padded)
    float* lse  = sm + 128 * 129;       // 256
    float* red  = sm + 128 * 129 + 256; // 128
    const int tid = threadIdx.x;
    for (int i = tid; i < BS * NP; i += 256) {
        const int r = i >> 7, c = i & 127;
        sims[r * 129 + c] = g_sim[i];
    }
    __syncthreads();
    const int i = tid & 127;
    if (tid < 128) {
        float m = -1e30f;
        for (int j = 0; j < 128; j++) m = fmaxf(m, sims[i * 129 + j]);
        float s = 0.0f;
        for (int j = 0; j < 128; j++) s += expf(sims[i * 129 + j] - m);
        lse[i] = m + logf(s);
    } else {
        float m = -1e30f;
        for (int j = 0; j < 128; j++) m = fmaxf(m, sims[j * 129 + i]);
        float s = 0.0f;
        for (int j = 0; j < 128; j++) s += expf(sims[j * 129 + i] - m);
        lse[128 + i] = m + logf(s);
    }
    __syncthreads();
    if (tid < 128)
        red[i] = sims[i * 129 + i] - 0.5f * (lse[i] + lse[128 + i]);
    __syncthreads();
    for (int st = 64; st > 0; st >>= 1) {
        if (tid < st) red[tid] += red[tid + st];
        __syncthreads();
    }
    if (tid == 0) out[0] = -red[0] / 128.0f;
}

// ---------------------------------------------------------------------------
extern "C" void kernel_launch(void* const* d_in, const int* in_sizes, int n_in,
                              void* d_out, int out_size) {
    const float* patch = (const float*)d_in[0];  // (128, 36, 768)
    const float* word  = (const float*)d_in[1];  // (128, 80, 768)
    const float* L     = (const float*)d_in[2];  // (768, 768)
    const float* Ww    = (const float*)d_in[3];  // (80, 80)
    const float* Wp    = (const float*)d_in[4];  // (36, 36)
    const float* Ww2   = (const float*)d_in[5];  // (80, 80)
    const float* Wp2   = (const float*)d_in[6];  // (36, 36)
    float* out = (float*)d_out;

    const int smem_k1 = 5376 * 4;
    const int smem_k2 = 25392 * 4;
    const int smem_k3 = 22544 * 4;
    const int smem_k4 = (128 * 129 + 256 + 128) * 4;
    cudaFuncSetAttribute(k1_plgemm, cudaFuncAttributeMaxDynamicSharedMemorySize, smem_k1);
    cudaFuncSetAttribute(k2_fine,   cudaFuncAttributeMaxDynamicSharedMemorySize, smem_k2);
    cudaFuncSetAttribute(k3_stage2, cudaFuncAttributeMaxDynamicSharedMemorySize, smem_k3);
    cudaFuncSetAttribute(k4_loss,   cudaFuncAttributeMaxDynamicSharedMemorySize, smem_k4);

    k1_plgemm<<<dim3(8, 36), 256, smem_k1>>>(patch, L);
    k2_fine<<<dim3(NP / PT, BS), 320, smem_k2>>>(word, Ww, Wp);
    k3_stage2<<<BS, 128, smem_k3>>>(Ww2, Wp2);
    k4_loss<<<1, 256, smem_k4>>>(out);
}